// round 1
// baseline (speedup 1.0000x reference)
#include <cuda_runtime.h>
#include <math.h>

// ======================= compile-time structure constants =======================
// For each 3-index c (35 sorted triples of 0..6): 6 terms (a,b,sign) where
// a,b index the 21 sorted pairs and sign is the permutation parity of
// (pair_a, pair_b, triple_c) as a permutation of (0..6).
struct Tables {
  signed char   ta[35][6];
  signed char   tb[35][6];
  float         ts[35][6];
  unsigned char p2i[256];
  unsigned char p2j[256];
};

constexpr Tables makeTables() {
  Tables T{};
  int c = 0;
  for (int x = 0; x < 7; x++)
    for (int y = x + 1; y < 7; y++)
      for (int z = y + 1; z < 7; z++) {
        int comp[4] = {0, 0, 0, 0};
        int m = 0;
        for (int e = 0; e < 7; e++)
          if (e != x && e != y && e != z) comp[m++] = e;
        int t = 0;
        for (int u = 0; u < 4; u++)
          for (int v = u + 1; v < 4; v++) {
            int a0 = comp[u], a1 = comp[v];
            int b0 = -1, b1 = -1;
            for (int e = 0; e < 4; e++) {
              if (e != u && e != v) { if (b0 < 0) b0 = comp[e]; else b1 = comp[e]; }
            }
            int perm[7] = {a0, a1, b0, b1, x, y, z};
            int inv = 0;
            for (int q = 0; q < 7; q++)
              for (int r = q + 1; r < 7; r++)
                if (perm[q] > perm[r]) inv++;
            T.ts[c][t] = (inv & 1) ? -1.0f : 1.0f;
            T.ta[c][t] = (signed char)(6 * a0 - a0 * (a0 - 1) / 2 + (a1 - a0 - 1));
            T.tb[c][t] = (signed char)(6 * b0 - b0 * (b0 - 1) / 2 + (b1 - b0 - 1));
            t++;
          }
        c++;
      }
  int p = 0;
  for (int i = 0; i < 21; i++)
    for (int j = i; j < 21; j++) {
      T.p2i[p] = (unsigned char)i;
      T.p2j[p] = (unsigned char)j;
      p++;
    }
  for (; p < 256; p++) { T.p2i[p] = 0; T.p2j[p] = 0; }
  return T;
}

constexpr Tables hT = makeTables();      // compile-time (register indexing)
__constant__ Tables dT = makeTables();   // runtime lookups

// ======================= device scratch (no allocations allowed) ================
#define NMAX   4096
#define NBLK   148
#define NPAIR  231
#define NK     77
#define NC     35
#define PH_LD  82   // Phi smem row stride (even for 8B alignment, odd/16 for banks)

__device__ float g_w[NMAX];
__device__ float g_part[NBLK][256 * 80];
__device__ float g_S[NPAIR * NK];

// ======================= f32x2 packed-FMA helpers ===============================
__device__ __forceinline__ unsigned long long pack2(float x) {
  unsigned long long r;
  asm("mov.b64 %0, {%1, %1};" : "=l"(r) : "f"(x));
  return r;
}
__device__ __forceinline__ void ffma2(unsigned long long &d, unsigned long long a,
                                      unsigned long long b) {
  asm("fma.rn.f32x2 %0, %1, %2, %0;" : "+l"(d) : "l"(a), "l"(b));
}
__device__ __forceinline__ float2 unpack2(unsigned long long v) {
  float2 f;
  asm("mov.b64 {%0, %1}, %2;" : "=f"(f.x), "=f"(f.y) : "l"(v));
  return f;
}

// ======================= kernel 1: Monte-Carlo weights ==========================
__global__ void k_weights(const float* __restrict__ metric, int n) {
  __shared__ float red[256];
  __shared__ float invsum;
  float local = 0.f;
  for (int idx = threadIdx.x; idx < n; idx += 256) {
    float a[7][7];
#pragma unroll
    for (int r = 0; r < 7; r++)
#pragma unroll
      for (int cc = 0; cc < 7; cc++) a[r][cc] = metric[idx * 49 + r * 7 + cc];
    float det = 1.f;
    for (int k = 0; k < 7; k++) {
      int piv = k;
      float mx = fabsf(a[k][k]);
      for (int r = k + 1; r < 7; r++) {
        float v = fabsf(a[r][k]);
        if (v > mx) { mx = v; piv = r; }
      }
      if (piv != k) {
        det = -det;
        for (int cc = 0; cc < 7; cc++) {
          float tmp = a[k][cc]; a[k][cc] = a[piv][cc]; a[piv][cc] = tmp;
        }
      }
      float akk = a[k][k];
      det *= akk;
      float inv = (akk != 0.f) ? 1.f / akk : 0.f;
      for (int r = k + 1; r < 7; r++) {
        float f = a[r][k] * inv;
        for (int cc = k + 1; cc < 7; cc++) a[r][cc] -= f * a[k][cc];
      }
    }
    float vol = sqrtf(fabsf(det));
    g_w[idx] = vol;
    local += vol;
  }
  red[threadIdx.x] = local;
  __syncthreads();
  for (int s = 128; s > 0; s >>= 1) {
    if (threadIdx.x < s) red[threadIdx.x] += red[threadIdx.x + s];
    __syncthreads();
  }
  if (threadIdx.x == 0) invsum = 1.f / red[0];
  __syncthreads();
  for (int idx = threadIdx.x; idx < n; idx += 256) g_w[idx] *= invsum;
}

// ======================= D-compute: fully unrolled, indices baked in ============
template <int C, int T>
__device__ __forceinline__ float dterms(const float (&wi)[21], const float (&wj)[21],
                                        float acc) {
  constexpr int a = hT.ta[C][T];
  constexpr int b = hT.tb[C][T];
  if constexpr (hT.ts[C][T] > 0.f)
    acc = fmaf(wi[a], wj[b], acc);
  else
    acc = fmaf(-wi[a], wj[b], acc);
  if constexpr (T + 1 < 6) return dterms<C, T + 1>(wi, wj, acc);
  return acc;
}

template <int C>
__device__ __forceinline__ void dAll(float* Ds, int tid, const float (&wi)[21],
                                     const float (&wj)[21]) {
  Ds[C * 256 + tid] = dterms<C, 0>(wi, wj, 0.0f);
  if constexpr (C + 1 < 35) dAll<C + 1>(Ds, tid, wi, wj);
}

// ======================= kernel 2: fused D + big contraction ====================
// grid 148, 256 threads. Each block: n-slice -> partial S[231][77] in f32x2 regs.
__global__ void __launch_bounds__(256, 1)
k_main(const float* __restrict__ omega, const float* __restrict__ Phi, int n,
       int chunk) {
  extern __shared__ float sm[];
  float* Ds  = sm;                          // [35][256]
  float* Phs = sm + 35 * 256;               // [35][PH_LD]
  float* Ws  = sm + 35 * 256 + 35 * PH_LD;  // [441]

  const int tid   = threadIdx.x;
  const int lane  = tid & 31;
  const int warp  = tid >> 5;
  const int pbase = lane * 8;   // 8 pairs per lane (256 >= 231, padded)
  const int kbase = warp * 10;  // 10 k per warp (80 >= 77, padded w/ zeros)
  const int pi = dT.p2i[tid];
  const int pj = dT.p2j[tid];

  unsigned long long acc[8][5];
#pragma unroll
  for (int a = 0; a < 8; a++)
#pragma unroll
    for (int b = 0; b < 5; b++) acc[a][b] = 0ull;

  int n0 = blockIdx.x * chunk;
  int n1 = n0 + chunk;
  if (n1 > n) n1 = n;

  for (int nn = n0; nn < n1; nn++) {
    const float wn = g_w[nn];
    const float* og = omega + (size_t)nn * 441;
    for (int idx = tid; idx < 441; idx += 256) Ws[idx] = og[idx];
    const float* pg = Phi + (size_t)nn * 2695;
    for (int idx = tid; idx < 2695; idx += 256) {
      int k = idx / 35;
      int c = idx - k * 35;
      Phs[c * PH_LD + k] = pg[idx] * wn;   // transpose to [c][k], fold weight
    }
    if (tid < 35 * 3) {
      int c = tid / 3, r = tid - c * 3;
      Phs[c * PH_LD + 77 + r] = 0.f;       // zero k-padding
    }
    __syncthreads();

    {  // D phase: one (i,j) pair per thread, everything in registers
      float wi[21], wj[21];
      const float* Wi = &Ws[pi * 21];
      const float* Wj = &Ws[pj * 21];
#pragma unroll
      for (int a = 0; a < 21; a++) { wi[a] = Wi[a]; wj[a] = Wj[a]; }
      dAll<0>(Ds, tid, wi, wj);
    }
    __syncthreads();

    // GEMM phase: S[p][k] += sum_c D[p][c] * Phw[k][c], packed f32x2 over k
#pragma unroll 1
    for (int c = 0; c < 35; c++) {
      const float4 d0 = *(const float4*)&Ds[c * 256 + pbase];
      const float4 d1 = *(const float4*)&Ds[c * 256 + pbase + 4];
      unsigned long long dd[8];
      dd[0] = pack2(d0.x); dd[1] = pack2(d0.y); dd[2] = pack2(d0.z); dd[3] = pack2(d0.w);
      dd[4] = pack2(d1.x); dd[5] = pack2(d1.y); dd[6] = pack2(d1.z); dd[7] = pack2(d1.w);
      unsigned long long ph[5];
#pragma unroll
      for (int u = 0; u < 5; u++)
        ph[u] = *(const unsigned long long*)&Phs[c * PH_LD + kbase + 2 * u];
#pragma unroll
      for (int p = 0; p < 8; p++)
#pragma unroll
        for (int u = 0; u < 5; u++) ffma2(acc[p][u], dd[p], ph[u]);
    }
    __syncthreads();
  }

  float* outp = g_part[blockIdx.x];
#pragma unroll
  for (int p = 0; p < 8; p++)
#pragma unroll
    for (int u = 0; u < 5; u++) {
      float2 f = unpack2(acc[p][u]);
      *(float2*)&outp[(pbase + p) * 80 + kbase + 2 * u] = f;
    }
}

// ======================= kernel 3: reduce partials, emit Y ======================
__global__ void k_reduceY(float* __restrict__ out, int writeY) {
  int idx = blockIdx.x * blockDim.x + threadIdx.x;
  if (idx >= 441 * 77) return;
  int i = idx / 1617;
  int rem = idx - i * 1617;
  int j = rem / 77;
  int k = rem - j * 77;
  int lo = i < j ? i : j;
  int hi = i < j ? j : i;
  int p = lo * 21 - lo * (lo - 1) / 2 + (hi - lo);
  float s = 0.f;
#pragma unroll 4
  for (int b = 0; b < NBLK; b++) s += g_part[b][p * 80 + k];
  if (writeY) out[idx] = (j >= i) ? s : -s;
  if (i <= j) g_S[p * 77 + k] = s;
}

// ======================= kernel 4: M, Jacobi eigenvalues, sort ==================
__global__ void __launch_bounds__(1024, 1)
k_meig(float* __restrict__ out, int oM, int oE) {
  extern __shared__ float sm[];
  float* S = sm;                  // [231*77]
  float* A = sm + NPAIR * NK;     // [77*78]
  __shared__ int   rx[40], ry[40];
  __shared__ float rc[40], rs[40];
  const int tid = threadIdx.x;

  for (int idx = tid; idx < NPAIR * NK; idx += 1024) S[idx] = g_S[idx];
  __syncthreads();

  // M[k][l] = sum_p m_p S[p][k] S[p][l], m_p = 1 (i==j) else 2.  4x4 tiles.
  if (tid < 400) {
    int tk = (tid % 20) * 4, tl = (tid / 20) * 4;
    float m[4][4] = {};
    for (int p = 0; p < NPAIR; p++) {
      float wgt = (dT.p2i[p] == dT.p2j[p]) ? 1.f : 2.f;
      float sk[4], sl[4];
#pragma unroll
      for (int r = 0; r < 4; r++) {
        int kk = tk + r;
        sk[r] = (kk < 77) ? wgt * S[p * 77 + kk] : 0.f;
      }
#pragma unroll
      for (int r = 0; r < 4; r++) {
        int ll = tl + r;
        sl[r] = (ll < 77) ? S[p * 77 + ll] : 0.f;
      }
#pragma unroll
      for (int r = 0; r < 4; r++)
#pragma unroll
        for (int q = 0; q < 4; q++) m[r][q] = fmaf(sk[r], sl[q], m[r][q]);
    }
#pragma unroll
    for (int r = 0; r < 4; r++)
#pragma unroll
      for (int q = 0; q < 4; q++) {
        int kk = tk + r, ll = tl + q;
        if (kk < 77 && ll < 77) {
          out[oM + kk * 77 + ll] = m[r][q];
          A[kk * 78 + ll] = m[r][q];
        }
      }
  }
  __syncthreads();

  // Parallel cyclic Jacobi: 77 rounds/sweep, 38 disjoint rotations/round.
  for (int sweep = 0; sweep < 8; sweep++) {
    for (int r = 0; r < 77; r++) {
      if (tid >= 1 && tid < 39) {
        int m_ = tid;
        int x = (r + m_) % 77;
        int y = (r + 77 - m_) % 77;
        rx[m_] = x; ry[m_] = y;
        float app = A[x * 78 + x], aqq = A[y * 78 + y], apq = A[x * 78 + y];
        float c = 1.f, s = 0.f;
        if (fabsf(apq) > 1e-30f) {
          float th = (aqq - app) / (2.f * apq);
          float t  = copysignf(1.f, th) / (fabsf(th) + sqrtf(1.f + th * th));
          c = rsqrtf(1.f + t * t);
          s = t * c;
        }
        rc[m_] = c; rs[m_] = s;
      }
      __syncthreads();
      for (int idx = tid; idx < 38 * 77; idx += 1024) {  // row phase (Q^T A)
        int m_ = idx / 77 + 1, col = idx % 77;
        int x = rx[m_], y = ry[m_];
        float c = rc[m_], s = rs[m_];
        float ax = A[x * 78 + col], ay = A[y * 78 + col];
        A[x * 78 + col] = c * ax - s * ay;
        A[y * 78 + col] = s * ax + c * ay;
      }
      __syncthreads();
      for (int idx = tid; idx < 38 * 77; idx += 1024) {  // col phase ((Q^T A) Q)
        int m_ = idx / 77 + 1, row = idx % 77;
        int x = rx[m_], y = ry[m_];
        float c = rc[m_], s = rs[m_];
        float ax = A[row * 78 + x], ay = A[row * 78 + y];
        A[row * 78 + x] = c * ax - s * ay;
        A[row * 78 + y] = s * ax + c * ay;
      }
      __syncthreads();
    }
  }

  if (tid < 77) {  // descending rank sort of the diagonal
    float v = A[tid * 78 + tid];
    int rank = 0;
    for (int j = 0; j < 77; j++) {
      float u = A[j * 78 + j];
      rank += (u > v) || (u == v && j < tid);
    }
    out[oE + rank] = v;
  }
}

// ======================= launch =================================================
extern "C" void kernel_launch(void* const* d_in, const int* in_sizes, int n_in,
                              void* d_out, int out_size) {
  const float* omega  = (const float*)d_in[0];  // (n,21,21)
  const float* Phi    = (const float*)d_in[1];  // (n,77,35)
  const float* metric = (const float*)d_in[2];  // (n,7,7)
  int n = in_sizes[2] / 49;
  if (n > NMAX) n = NMAX;

  float* out = (float*)d_out;
  int oE = out_size - 77;
  int oM = oE - 77 * 77;
  int writeY = (out_size >= 33957 + 77 * 77 + 77) ? 1 : 0;

  k_weights<<<1, 256>>>(metric, n);

  int chunk = (n + NBLK - 1) / NBLK;
  size_t smMain = (size_t)(35 * 256 + 35 * PH_LD + 448) * sizeof(float);  // 49112 B
  k_main<<<NBLK, 256, smMain>>>(omega, Phi, n, chunk);

  k_reduceY<<<(441 * 77 + 255) / 256, 256>>>(out, writeY);

  size_t smEig = (size_t)(NPAIR * NK + 77 * 78) * sizeof(float);  // 95172 B
  cudaFuncSetAttribute(k_meig, cudaFuncAttributeMaxDynamicSharedMemorySize,
                       (int)smEig);
  k_meig<<<1, 1024, smEig>>>(out, oM, oE);
}

// round 2
// speedup vs baseline: 1.2718x; 1.2718x over previous
#include <cuda_runtime.h>
#include <math.h>

// ======================= compile-time structure constants =======================
struct Tables {
  signed char   ta[35][6];
  signed char   tb[35][6];
  float         ts[35][6];
  unsigned char p2i[256];
  unsigned char p2j[256];
};

constexpr Tables makeTables() {
  Tables T{};
  int c = 0;
  for (int x = 0; x < 7; x++)
    for (int y = x + 1; y < 7; y++)
      for (int z = y + 1; z < 7; z++) {
        int comp[4] = {0, 0, 0, 0};
        int m = 0;
        for (int e = 0; e < 7; e++)
          if (e != x && e != y && e != z) comp[m++] = e;
        int t = 0;
        for (int u = 0; u < 4; u++)
          for (int v = u + 1; v < 4; v++) {
            int a0 = comp[u], a1 = comp[v];
            int b0 = -1, b1 = -1;
            for (int e = 0; e < 4; e++) {
              if (e != u && e != v) { if (b0 < 0) b0 = comp[e]; else b1 = comp[e]; }
            }
            int perm[7] = {a0, a1, b0, b1, x, y, z};
            int inv = 0;
            for (int q = 0; q < 7; q++)
              for (int r = q + 1; r < 7; r++)
                if (perm[q] > perm[r]) inv++;
            T.ts[c][t] = (inv & 1) ? -1.0f : 1.0f;
            T.ta[c][t] = (signed char)(6 * a0 - a0 * (a0 - 1) / 2 + (a1 - a0 - 1));
            T.tb[c][t] = (signed char)(6 * b0 - b0 * (b0 - 1) / 2 + (b1 - b0 - 1));
            t++;
          }
        c++;
      }
  int p = 0;
  for (int i = 0; i < 21; i++)
    for (int j = i; j < 21; j++) {
      T.p2i[p] = (unsigned char)i;
      T.p2j[p] = (unsigned char)j;
      p++;
    }
  for (; p < 256; p++) { T.p2i[p] = 0; T.p2j[p] = 0; }
  return T;
}

constexpr Tables hT = makeTables();
__constant__ Tables dT = makeTables();

// ======================= device scratch =========================================
#define NMAX   4096
#define NBLK   148
#define NPAIR  231
#define NK     77
#define NC     35
#define PH_LD  82
#define ALD    79   // A leading dim, odd -> conflict-free column phase

__device__ float g_w[NMAX];
__device__ float g_part[NBLK][256 * 80];
__device__ float g_S[NPAIR * NK];

// ======================= f32x2 packed-FMA helpers ===============================
__device__ __forceinline__ unsigned long long pack2(float x) {
  unsigned long long r;
  asm("mov.b64 %0, {%1, %1};" : "=l"(r) : "f"(x));
  return r;
}
__device__ __forceinline__ void ffma2(unsigned long long &d, unsigned long long a,
                                      unsigned long long b) {
  asm("fma.rn.f32x2 %0, %1, %2, %0;" : "+l"(d) : "l"(a), "l"(b));
}
__device__ __forceinline__ float2 unpack2(unsigned long long v) {
  float2 f;
  asm("mov.b64 {%0, %1}, %2;" : "=f"(f.x), "=f"(f.y) : "l"(v));
  return f;
}

// ======================= kernel 1: Monte-Carlo weights ==========================
__global__ void k_weights(const float* __restrict__ metric, int n) {
  __shared__ float red[256];
  __shared__ float invsum;
  float local = 0.f;
  for (int idx = threadIdx.x; idx < n; idx += 256) {
    float a[7][7];
#pragma unroll
    for (int r = 0; r < 7; r++)
#pragma unroll
      for (int cc = 0; cc < 7; cc++) a[r][cc] = metric[idx * 49 + r * 7 + cc];
    float det = 1.f;
    for (int k = 0; k < 7; k++) {
      int piv = k;
      float mx = fabsf(a[k][k]);
      for (int r = k + 1; r < 7; r++) {
        float v = fabsf(a[r][k]);
        if (v > mx) { mx = v; piv = r; }
      }
      if (piv != k) {
        det = -det;
        for (int cc = 0; cc < 7; cc++) {
          float tmp = a[k][cc]; a[k][cc] = a[piv][cc]; a[piv][cc] = tmp;
        }
      }
      float akk = a[k][k];
      det *= akk;
      float inv = (akk != 0.f) ? 1.f / akk : 0.f;
      for (int r = k + 1; r < 7; r++) {
        float f = a[r][k] * inv;
        for (int cc = k + 1; cc < 7; cc++) a[r][cc] -= f * a[k][cc];
      }
    }
    float vol = sqrtf(fabsf(det));
    g_w[idx] = vol;
    local += vol;
  }
  red[threadIdx.x] = local;
  __syncthreads();
  for (int s = 128; s > 0; s >>= 1) {
    if (threadIdx.x < s) red[threadIdx.x] += red[threadIdx.x + s];
    __syncthreads();
  }
  if (threadIdx.x == 0) invsum = 1.f / red[0];
  __syncthreads();
  for (int idx = threadIdx.x; idx < n; idx += 256) g_w[idx] *= invsum;
}

// ======================= D-compute: fully unrolled ==============================
template <int C, int T>
__device__ __forceinline__ float dterms(const float (&wi)[21], const float (&wj)[21],
                                        float acc) {
  constexpr int a = hT.ta[C][T];
  constexpr int b = hT.tb[C][T];
  if constexpr (hT.ts[C][T] > 0.f)
    acc = fmaf(wi[a], wj[b], acc);
  else
    acc = fmaf(-wi[a], wj[b], acc);
  if constexpr (T + 1 < 6) return dterms<C, T + 1>(wi, wj, acc);
  return acc;
}

template <int C>
__device__ __forceinline__ void dAll(float* Ds, int tid, const float (&wi)[21],
                                     const float (&wj)[21]) {
  Ds[C * 256 + tid] = dterms<C, 0>(wi, wj, 0.0f);
  if constexpr (C + 1 < 35) dAll<C + 1>(Ds, tid, wi, wj);
}

// ======================= kernel 2: fused D + big contraction ====================
__global__ void __launch_bounds__(256, 1)
k_main(const float* __restrict__ omega, const float* __restrict__ Phi, int n,
       int chunk) {
  extern __shared__ float sm[];
  float* Ds  = sm;                          // [35][256]
  float* Phs = sm + 35 * 256;               // [35][PH_LD]
  float* Ws  = sm + 35 * 256 + 35 * PH_LD;  // [441]

  const int tid   = threadIdx.x;
  const int lane  = tid & 31;
  const int warp  = tid >> 5;
  const int pbase = lane * 8;
  const int kbase = warp * 10;
  const int pi = dT.p2i[tid];
  const int pj = dT.p2j[tid];

  unsigned long long acc[8][5];
#pragma unroll
  for (int a = 0; a < 8; a++)
#pragma unroll
    for (int b = 0; b < 5; b++) acc[a][b] = 0ull;

  int n0 = blockIdx.x * chunk;
  int n1 = n0 + chunk;
  if (n1 > n) n1 = n;

  for (int nn = n0; nn < n1; nn++) {
    const float wn = g_w[nn];
    const float* og = omega + (size_t)nn * 441;
    for (int idx = tid; idx < 441; idx += 256) Ws[idx] = og[idx];
    const float* pg = Phi + (size_t)nn * 2695;
    for (int idx = tid; idx < 2695; idx += 256) {
      int k = idx / 35;
      int c = idx - k * 35;
      Phs[c * PH_LD + k] = pg[idx] * wn;
    }
    if (tid < 35 * 3) {
      int c = tid / 3, r = tid - c * 3;
      Phs[c * PH_LD + 77 + r] = 0.f;
    }
    __syncthreads();

    {
      float wi[21], wj[21];
      const float* Wi = &Ws[pi * 21];
      const float* Wj = &Ws[pj * 21];
#pragma unroll
      for (int a = 0; a < 21; a++) { wi[a] = Wi[a]; wj[a] = Wj[a]; }
      dAll<0>(Ds, tid, wi, wj);
    }
    __syncthreads();

#pragma unroll 1
    for (int c = 0; c < 35; c++) {
      const float4 d0 = *(const float4*)&Ds[c * 256 + pbase];
      const float4 d1 = *(const float4*)&Ds[c * 256 + pbase + 4];
      unsigned long long dd[8];
      dd[0] = pack2(d0.x); dd[1] = pack2(d0.y); dd[2] = pack2(d0.z); dd[3] = pack2(d0.w);
      dd[4] = pack2(d1.x); dd[5] = pack2(d1.y); dd[6] = pack2(d1.z); dd[7] = pack2(d1.w);
      unsigned long long ph[5];
#pragma unroll
      for (int u = 0; u < 5; u++)
        ph[u] = *(const unsigned long long*)&Phs[c * PH_LD + kbase + 2 * u];
#pragma unroll
      for (int p = 0; p < 8; p++)
#pragma unroll
        for (int u = 0; u < 5; u++) ffma2(acc[p][u], dd[p], ph[u]);
    }
    __syncthreads();
  }

  float* outp = g_part[blockIdx.x];
#pragma unroll
  for (int p = 0; p < 8; p++)
#pragma unroll
    for (int u = 0; u < 5; u++) {
      float2 f = unpack2(acc[p][u]);
      *(float2*)&outp[(pbase + p) * 80 + kbase + 2 * u] = f;
    }
}

// ======================= kernel 3: reduce partials, emit Y ======================
__global__ void k_reduceY(float* __restrict__ out, int writeY) {
  int idx = blockIdx.x * blockDim.x + threadIdx.x;
  if (idx >= 441 * 77) return;
  int i = idx / 1617;
  int rem = idx - i * 1617;
  int j = rem / 77;
  int k = rem - j * 77;
  int lo = i < j ? i : j;
  int hi = i < j ? j : i;
  int p = lo * 21 - lo * (lo - 1) / 2 + (hi - lo);
  float s = 0.f;
#pragma unroll 4
  for (int b = 0; b < NBLK; b++) s += g_part[b][p * 80 + k];
  if (writeY) out[idx] = (j >= i) ? s : -s;
  if (i <= j) g_S[p * 77 + k] = s;
}

// ======================= kernel 4: M, Jacobi eigenvalues, sort ==================
// Parallel cyclic Jacobi, register-resident schedule:
//  - each thread owns up to 3 fixed (m, col) slots for the whole solve
//  - pair indices (x, y) advance by +1 mod 77 per round (register update)
//  - only (c, s) rotation params go through smem (broadcast loads)
__global__ void __launch_bounds__(1024, 1)
k_meig(float* __restrict__ out, int oM, int oE) {
  extern __shared__ float sm[];
  float* S = sm;                  // [231*77]
  float* A = sm + NPAIR * NK;     // [77*ALD]
  __shared__ float rc[40], rs[40];
  const int tid = threadIdx.x;

  for (int idx = tid; idx < NPAIR * NK; idx += 1024) S[idx] = g_S[idx];
  __syncthreads();

  // M[k][l] = sum_p m_p S[p][k] S[p][l]
  if (tid < 400) {
    int tk = (tid % 20) * 4, tl = (tid / 20) * 4;
    float m[4][4] = {};
    for (int p = 0; p < NPAIR; p++) {
      float wgt = (dT.p2i[p] == dT.p2j[p]) ? 1.f : 2.f;
      float sk[4], sl[4];
#pragma unroll
      for (int r = 0; r < 4; r++) {
        int kk = tk + r;
        sk[r] = (kk < 77) ? wgt * S[p * 77 + kk] : 0.f;
      }
#pragma unroll
      for (int r = 0; r < 4; r++) {
        int ll = tl + r;
        sl[r] = (ll < 77) ? S[p * 77 + ll] : 0.f;
      }
#pragma unroll
      for (int r = 0; r < 4; r++)
#pragma unroll
        for (int q = 0; q < 4; q++) m[r][q] = fmaf(sk[r], sl[q], m[r][q]);
    }
#pragma unroll
    for (int r = 0; r < 4; r++)
#pragma unroll
      for (int q = 0; q < 4; q++) {
        int kk = tk + r, ll = tl + q;
        if (kk < 77 && ll < 77) {
          out[oM + kk * 77 + ll] = m[r][q];
          A[kk * ALD + ll] = m[r][q];
        }
      }
  }
  __syncthreads();

  // ---- per-thread round-invariant schedule ----
  int mS[3], colS[3], xS[3], yS[3];
  bool actS[3];
#pragma unroll
  for (int s = 0; s < 3; s++) {
    int idx = tid + s * 1024;
    bool a = idx < 38 * 77;
    actS[s] = a;
    int mm = a ? (idx / 77 + 1) : 1;
    int cc = a ? (idx - (mm - 1) * 77) : 0;
    mS[s] = mm;
    colS[s] = cc;
    xS[s] = mm;            // (0 + m) % 77, m in 1..38
    yS[s] = 77 - mm;       // (0 + 77 - m) % 77
  }
  const bool isRot = (tid >= 1 && tid < 39);
  int xr = isRot ? tid : 1;
  int yr = isRot ? 77 - tid : 76;

  for (int sweep = 0; sweep < 8; sweep++) {
#pragma unroll 1
    for (int r = 0; r < 77; r++) {
      if (isRot) {
        float app = A[xr * ALD + xr], aqq = A[yr * ALD + yr],
              apq = A[xr * ALD + yr];
        float c = 1.f, s = 0.f;
        if (fabsf(apq) > 1e-30f) {
          float th = (aqq - app) / (2.f * apq);
          float t  = copysignf(1.f, th) / (fabsf(th) + sqrtf(1.f + th * th));
          c = rsqrtf(1.f + t * t);
          s = t * c;
        }
        rc[tid] = c; rs[tid] = s;
      }
      __syncthreads();

      float cv[3], sv[3], ax[3], ay[3];
#pragma unroll
      for (int s2 = 0; s2 < 3; s2++)
        if (actS[s2]) {
          cv[s2] = rc[mS[s2]]; sv[s2] = rs[mS[s2]];
          ax[s2] = A[xS[s2] * ALD + colS[s2]];
          ay[s2] = A[yS[s2] * ALD + colS[s2]];
        }
#pragma unroll
      for (int s2 = 0; s2 < 3; s2++)
        if (actS[s2]) {
          A[xS[s2] * ALD + colS[s2]] = cv[s2] * ax[s2] - sv[s2] * ay[s2];
          A[yS[s2] * ALD + colS[s2]] = sv[s2] * ax[s2] + cv[s2] * ay[s2];
        }
      __syncthreads();

#pragma unroll
      for (int s2 = 0; s2 < 3; s2++)
        if (actS[s2]) {
          ax[s2] = A[colS[s2] * ALD + xS[s2]];
          ay[s2] = A[colS[s2] * ALD + yS[s2]];
        }
#pragma unroll
      for (int s2 = 0; s2 < 3; s2++)
        if (actS[s2]) {
          A[colS[s2] * ALD + xS[s2]] = cv[s2] * ax[s2] - sv[s2] * ay[s2];
          A[colS[s2] * ALD + yS[s2]] = sv[s2] * ax[s2] + cv[s2] * ay[s2];
        }
      __syncthreads();

#pragma unroll
      for (int s2 = 0; s2 < 3; s2++) {
        xS[s2] = (xS[s2] + 1 == 77) ? 0 : xS[s2] + 1;
        yS[s2] = (yS[s2] + 1 == 77) ? 0 : yS[s2] + 1;
      }
      xr = (xr + 1 == 77) ? 0 : xr + 1;
      yr = (yr + 1 == 77) ? 0 : yr + 1;
    }
  }

  if (tid < 77) {
    float v = A[tid * ALD + tid];
    int rank = 0;
    for (int j = 0; j < 77; j++) {
      float u = A[j * ALD + j];
      rank += (u > v) || (u == v && j < tid);
    }
    out[oE + rank] = v;
  }
}

// ======================= launch =================================================
extern "C" void kernel_launch(void* const* d_in, const int* in_sizes, int n_in,
                              void* d_out, int out_size) {
  const float* omega  = (const float*)d_in[0];
  const float* Phi    = (const float*)d_in[1];
  const float* metric = (const float*)d_in[2];
  int n = in_sizes[2] / 49;
  if (n > NMAX) n = NMAX;

  float* out = (float*)d_out;
  int oE = out_size - 77;
  int oM = oE - 77 * 77;
  int writeY = (out_size >= 33957 + 77 * 77 + 77) ? 1 : 0;

  k_weights<<<1, 256>>>(metric, n);

  int chunk = (n + NBLK - 1) / NBLK;
  size_t smMain = (size_t)(35 * 256 + 35 * PH_LD + 448) * sizeof(float);
  k_main<<<NBLK, 256, smMain>>>(omega, Phi, n, chunk);

  k_reduceY<<<(441 * 77 + 255) / 256, 256>>>(out, writeY);

  size_t smEig = (size_t)(NPAIR * NK + 77 * ALD) * sizeof(float);
  cudaFuncSetAttribute(k_meig, cudaFuncAttributeMaxDynamicSharedMemorySize,
                       (int)smEig);
  k_meig<<<1, 1024, smEig>>>(out, oM, oE);
}

// round 3
// speedup vs baseline: 1.6835x; 1.3237x over previous
#include <cuda_runtime.h>
#include <math.h>

// ======================= compile-time structure constants =======================
struct Tables {
  signed char   ta[35][6];
  signed char   tb[35][6];
  float         ts[35][6];
  unsigned char p2i[256];
  unsigned char p2j[256];
};

constexpr Tables makeTables() {
  Tables T{};
  int c = 0;
  for (int x = 0; x < 7; x++)
    for (int y = x + 1; y < 7; y++)
      for (int z = y + 1; z < 7; z++) {
        int comp[4] = {0, 0, 0, 0};
        int m = 0;
        for (int e = 0; e < 7; e++)
          if (e != x && e != y && e != z) comp[m++] = e;
        int t = 0;
        for (int u = 0; u < 4; u++)
          for (int v = u + 1; v < 4; v++) {
            int a0 = comp[u], a1 = comp[v];
            int b0 = -1, b1 = -1;
            for (int e = 0; e < 4; e++) {
              if (e != u && e != v) { if (b0 < 0) b0 = comp[e]; else b1 = comp[e]; }
            }
            int perm[7] = {a0, a1, b0, b1, x, y, z};
            int inv = 0;
            for (int q = 0; q < 7; q++)
              for (int r = q + 1; r < 7; r++)
                if (perm[q] > perm[r]) inv++;
            T.ts[c][t] = (inv & 1) ? -1.0f : 1.0f;
            T.ta[c][t] = (signed char)(6 * a0 - a0 * (a0 - 1) / 2 + (a1 - a0 - 1));
            T.tb[c][t] = (signed char)(6 * b0 - b0 * (b0 - 1) / 2 + (b1 - b0 - 1));
            t++;
          }
        c++;
      }
  int p = 0;
  for (int i = 0; i < 21; i++)
    for (int j = i; j < 21; j++) {
      T.p2i[p] = (unsigned char)i;
      T.p2j[p] = (unsigned char)j;
      p++;
    }
  for (; p < 256; p++) { T.p2i[p] = 0; T.p2j[p] = 0; }
  return T;
}

constexpr Tables hT = makeTables();
__constant__ Tables dT = makeTables();

// ======================= device scratch =========================================
#define NMAX   4096
#define NCHK   148      // n-chunks
#define NGRID  296      // 2 pair-halves x 148 n-chunks
#define NPAIR  231
#define NK     77
#define NC     35
#define PH_LD  82
#define ALD    79
#define SWEEPS 5

__device__ float g_w[NMAX];
__device__ float g_part[NGRID][128 * 80];
__device__ float g_S[NPAIR * NK];

// ======================= f32x2 packed-FMA helpers ===============================
__device__ __forceinline__ unsigned long long pack2(float x) {
  unsigned long long r;
  asm("mov.b64 %0, {%1, %1};" : "=l"(r) : "f"(x));
  return r;
}
__device__ __forceinline__ void ffma2(unsigned long long &d, unsigned long long a,
                                      unsigned long long b) {
  asm("fma.rn.f32x2 %0, %1, %2, %0;" : "+l"(d) : "l"(a), "l"(b));
}
__device__ __forceinline__ float2 unpack2(unsigned long long v) {
  float2 f;
  asm("mov.b64 {%0, %1}, %2;" : "=f"(f.x), "=f"(f.y) : "l"(v));
  return f;
}

// ======================= kernel 1: Monte-Carlo weights ==========================
__global__ void __launch_bounds__(1024, 1)
k_weights(const float* __restrict__ metric, int n) {
  __shared__ float red[1024];
  __shared__ float invsum;
  float local = 0.f;
  for (int idx = threadIdx.x; idx < n; idx += 1024) {
    float a[7][7];
#pragma unroll
    for (int r = 0; r < 7; r++)
#pragma unroll
      for (int cc = 0; cc < 7; cc++) a[r][cc] = metric[idx * 49 + r * 7 + cc];
    float det = 1.f;
    for (int k = 0; k < 7; k++) {
      int piv = k;
      float mx = fabsf(a[k][k]);
      for (int r = k + 1; r < 7; r++) {
        float v = fabsf(a[r][k]);
        if (v > mx) { mx = v; piv = r; }
      }
      if (piv != k) {
        det = -det;
        for (int cc = 0; cc < 7; cc++) {
          float tmp = a[k][cc]; a[k][cc] = a[piv][cc]; a[piv][cc] = tmp;
        }
      }
      float akk = a[k][k];
      det *= akk;
      float inv = (akk != 0.f) ? 1.f / akk : 0.f;
      for (int r = k + 1; r < 7; r++) {
        float f = a[r][k] * inv;
        for (int cc = k + 1; cc < 7; cc++) a[r][cc] -= f * a[k][cc];
      }
    }
    float vol = sqrtf(fabsf(det));
    g_w[idx] = vol;
    local += vol;
  }
  red[threadIdx.x] = local;
  __syncthreads();
  for (int s = 512; s > 0; s >>= 1) {
    if (threadIdx.x < s) red[threadIdx.x] += red[threadIdx.x + s];
    __syncthreads();
  }
  if (threadIdx.x == 0) invsum = 1.f / red[0];
  __syncthreads();
  for (int idx = threadIdx.x; idx < n; idx += 1024) g_w[idx] *= invsum;
}

// ======================= D-compute: fully unrolled ==============================
template <int C, int T>
__device__ __forceinline__ float dterms(const float (&wi)[21], const float (&wj)[21],
                                        float acc) {
  constexpr int a = hT.ta[C][T];
  constexpr int b = hT.tb[C][T];
  if constexpr (hT.ts[C][T] > 0.f)
    acc = fmaf(wi[a], wj[b], acc);
  else
    acc = fmaf(-wi[a], wj[b], acc);
  if constexpr (T + 1 < 6) return dterms<C, T + 1>(wi, wj, acc);
  return acc;
}

template <int C>
__device__ __forceinline__ void dAll(float* Ds, int tid, const float (&wi)[21],
                                     const float (&wj)[21]) {
  Ds[C * 256 + tid] = dterms<C, 0>(wi, wj, 0.0f);
  if constexpr (C + 1 < 35) dAll<C + 1>(Ds, tid, wi, wj);
}

// ======================= kernel 2: fused D + big contraction ====================
// grid 296 = (148 n-chunks) x (2 pair-halves). 2 blocks/SM, prefetched loads.
__global__ void __launch_bounds__(256, 2)
k_main(const float* __restrict__ omega, const float* __restrict__ Phi, int n,
       int chunk) {
  extern __shared__ float sm[];
  float* Ds  = sm;                          // [35][256]
  float* Phs = sm + 35 * 256;               // [35][PH_LD]
  float* Ws  = sm + 35 * 256 + 35 * PH_LD;  // [441]

  const int tid   = threadIdx.x;
  const int lane  = tid & 31;
  const int warp  = tid >> 5;
  const int h     = blockIdx.x & 1;         // pair half
  const int nc    = blockIdx.x >> 1;        // n-chunk
  const int pbase = h * 128 + lane * 4;     // 4 global pairs per lane
  const int kbase = warp * 10;              // 10 k per warp
  const int pi = dT.p2i[tid];
  const int pj = dT.p2j[tid];

  // static Phi-transpose addresses for this thread
  int phAddr[11];
#pragma unroll
  for (int j = 0; j < 11; j++) {
    int idx = tid + j * 256;
    int k = idx / 35;
    int c = idx - k * 35;
    phAddr[j] = c * PH_LD + k;   // may exceed range for idx>=2695 (guarded)
  }

  // zero k-padding of Phs once (never overwritten: k<77 always)
  if (tid < 35 * 5) {
    int c = tid / 5, r = tid - c * 5;
    Phs[c * PH_LD + 77 + r] = 0.f;
  }

  unsigned long long acc[4][5];
#pragma unroll
  for (int a = 0; a < 4; a++)
#pragma unroll
    for (int b = 0; b < 5; b++) acc[a][b] = 0ull;

  int n0 = nc * chunk;
  int n1 = n0 + chunk;
  if (n1 > n) n1 = n;

  float rO0 = 0.f, rO1 = 0.f, rP[11];
#pragma unroll
  for (int j = 0; j < 11; j++) rP[j] = 0.f;

  if (n0 < n1) {  // prefetch first iteration
    const float* og = omega + (size_t)n0 * 441;
    rO0 = og[tid];
    if (tid + 256 < 441) rO1 = og[tid + 256];
    const float* pg = Phi + (size_t)n0 * 2695;
#pragma unroll
    for (int j = 0; j < 11; j++) {
      int idx = tid + j * 256;
      if (idx < 2695) rP[j] = pg[idx];
    }
  }

  for (int nn = n0; nn < n1; nn++) {
    const float wn = g_w[nn];
    __syncthreads();   // previous GEMM done reading smem
    Ws[tid] = rO0;
    if (tid + 256 < 441) Ws[tid + 256] = rO1;
#pragma unroll
    for (int j = 0; j < 11; j++) {
      int idx = tid + j * 256;
      if (idx < 2695) Phs[phAddr[j]] = rP[j] * wn;
    }
    __syncthreads();

    // prefetch next n while D+GEMM run
    {
      int nx = (nn + 1 < n1) ? nn + 1 : nn;
      const float* og = omega + (size_t)nx * 441;
      rO0 = og[tid];
      if (tid + 256 < 441) rO1 = og[tid + 256];
      const float* pg = Phi + (size_t)nx * 2695;
#pragma unroll
      for (int j = 0; j < 11; j++) {
        int idx = tid + j * 256;
        if (idx < 2695) rP[j] = pg[idx];
      }
    }

    {  // D phase: pair tid, all in registers
      float wi[21], wj[21];
      const float* Wi = &Ws[pi * 21];
      const float* Wj = &Ws[pj * 21];
#pragma unroll
      for (int a = 0; a < 21; a++) { wi[a] = Wi[a]; wj[a] = Wj[a]; }
      dAll<0>(Ds, tid, wi, wj);
    }
    __syncthreads();

    // GEMM: acc[p][u] += D[pbase+p][c] * Phw[kbase+2u..][c]
#pragma unroll 1
    for (int c = 0; c < 35; c++) {
      const float4 d0 = *(const float4*)&Ds[c * 256 + pbase];
      unsigned long long dd[4];
      dd[0] = pack2(d0.x); dd[1] = pack2(d0.y);
      dd[2] = pack2(d0.z); dd[3] = pack2(d0.w);
      unsigned long long ph[5];
#pragma unroll
      for (int u = 0; u < 5; u++)
        ph[u] = *(const unsigned long long*)&Phs[c * PH_LD + kbase + 2 * u];
#pragma unroll
      for (int p = 0; p < 4; p++)
#pragma unroll
        for (int u = 0; u < 5; u++) ffma2(acc[p][u], dd[p], ph[u]);
    }
  }

  float* outp = g_part[blockIdx.x];
#pragma unroll
  for (int p = 0; p < 4; p++)
#pragma unroll
    for (int u = 0; u < 5; u++) {
      float2 f = unpack2(acc[p][u]);
      *(float2*)&outp[(lane * 4 + p) * 80 + kbase + 2 * u] = f;
    }
}

// ======================= kernel 3: reduce partials, emit Y ======================
__global__ void k_reduceY(float* __restrict__ out, int writeY) {
  int idx = blockIdx.x * blockDim.x + threadIdx.x;
  if (idx >= 441 * 77) return;
  int i = idx / 1617;
  int rem = idx - i * 1617;
  int j = rem / 77;
  int k = rem - j * 77;
  int lo = i < j ? i : j;
  int hi = i < j ? j : i;
  int p = lo * 21 - lo * (lo - 1) / 2 + (hi - lo);
  int hh = p >> 7;          // pair half
  int lp = p & 127;
  float s = 0.f;
#pragma unroll 4
  for (int b = 0; b < NCHK; b++) s += g_part[2 * b + hh][lp * 80 + k];
  if (writeY) out[idx] = (j >= i) ? s : -s;
  if (i <= j) g_S[p * 77 + k] = s;
}

// ======================= kernel 4: M, Jacobi eigenvalues, sort ==================
__global__ void __launch_bounds__(1024, 1)
k_meig(float* __restrict__ out, int oM, int oE) {
  extern __shared__ float sm[];
  float* S = sm;                  // [231*77]
  float* A = sm + NPAIR * NK;     // [77*ALD]
  __shared__ float rc[40], rs[40];
  const int tid = threadIdx.x;

  for (int idx = tid; idx < NPAIR * NK; idx += 1024) S[idx] = g_S[idx];
  __syncthreads();

  if (tid < 400) {
    int tk = (tid % 20) * 4, tl = (tid / 20) * 4;
    float m[4][4] = {};
    for (int p = 0; p < NPAIR; p++) {
      float wgt = (dT.p2i[p] == dT.p2j[p]) ? 1.f : 2.f;
      float sk[4], sl[4];
#pragma unroll
      for (int r = 0; r < 4; r++) {
        int kk = tk + r;
        sk[r] = (kk < 77) ? wgt * S[p * 77 + kk] : 0.f;
      }
#pragma unroll
      for (int r = 0; r < 4; r++) {
        int ll = tl + r;
        sl[r] = (ll < 77) ? S[p * 77 + ll] : 0.f;
      }
#pragma unroll
      for (int r = 0; r < 4; r++)
#pragma unroll
        for (int q = 0; q < 4; q++) m[r][q] = fmaf(sk[r], sl[q], m[r][q]);
    }
#pragma unroll
    for (int r = 0; r < 4; r++)
#pragma unroll
      for (int q = 0; q < 4; q++) {
        int kk = tk + r, ll = tl + q;
        if (kk < 77 && ll < 77) {
          out[oM + kk * 77 + ll] = m[r][q];
          A[kk * ALD + ll] = m[r][q];
        }
      }
  }
  __syncthreads();

  int mS[3], colS[3], xS[3], yS[3];
  bool actS[3];
#pragma unroll
  for (int s = 0; s < 3; s++) {
    int idx = tid + s * 1024;
    bool a = idx < 38 * 77;
    actS[s] = a;
    int mm = a ? (idx / 77 + 1) : 1;
    int cc = a ? (idx - (mm - 1) * 77) : 0;
    mS[s] = mm;
    colS[s] = cc;
    xS[s] = mm;
    yS[s] = 77 - mm;
  }
  const bool isRot = (tid >= 1 && tid < 39);
  int xr = isRot ? tid : 1;
  int yr = isRot ? 77 - tid : 76;

  for (int sweep = 0; sweep < SWEEPS; sweep++) {
#pragma unroll 1
    for (int r = 0; r < 77; r++) {
      if (isRot) {
        float app = A[xr * ALD + xr], aqq = A[yr * ALD + yr],
              apq = A[xr * ALD + yr];
        float c = 1.f, s = 0.f;
        if (fabsf(apq) > 1e-30f) {
          float th = __fdividef(aqq - app, 2.f * apq);
          float sq = __fsqrt_rn(fmaf(th, th, 1.f));
          float t  = __fdividef(copysignf(1.f, th), fabsf(th) + sq);
          c = rsqrtf(fmaf(t, t, 1.f));
          s = t * c;
        }
        rc[tid] = c; rs[tid] = s;
      }
      __syncthreads();

      float cv[3], sv[3], ax[3], ay[3];
#pragma unroll
      for (int s2 = 0; s2 < 3; s2++)
        if (actS[s2]) {
          cv[s2] = rc[mS[s2]]; sv[s2] = rs[mS[s2]];
          ax[s2] = A[xS[s2] * ALD + colS[s2]];
          ay[s2] = A[yS[s2] * ALD + colS[s2]];
        }
#pragma unroll
      for (int s2 = 0; s2 < 3; s2++)
        if (actS[s2]) {
          A[xS[s2] * ALD + colS[s2]] = cv[s2] * ax[s2] - sv[s2] * ay[s2];
          A[yS[s2] * ALD + colS[s2]] = sv[s2] * ax[s2] + cv[s2] * ay[s2];
        }
      __syncthreads();

#pragma unroll
      for (int s2 = 0; s2 < 3; s2++)
        if (actS[s2]) {
          ax[s2] = A[colS[s2] * ALD + xS[s2]];
          ay[s2] = A[colS[s2] * ALD + yS[s2]];
        }
#pragma unroll
      for (int s2 = 0; s2 < 3; s2++)
        if (actS[s2]) {
          A[colS[s2] * ALD + xS[s2]] = cv[s2] * ax[s2] - sv[s2] * ay[s2];
          A[colS[s2] * ALD + yS[s2]] = sv[s2] * ax[s2] + cv[s2] * ay[s2];
        }
      __syncthreads();

#pragma unroll
      for (int s2 = 0; s2 < 3; s2++) {
        xS[s2] = (xS[s2] + 1 == 77) ? 0 : xS[s2] + 1;
        yS[s2] = (yS[s2] + 1 == 77) ? 0 : yS[s2] + 1;
      }
      xr = (xr + 1 == 77) ? 0 : xr + 1;
      yr = (yr + 1 == 77) ? 0 : yr + 1;
    }
  }

  if (tid < 77) {
    float v = A[tid * ALD + tid];
    int rank = 0;
    for (int j = 0; j < 77; j++) {
      float u = A[j * ALD + j];
      rank += (u > v) || (u == v && j < tid);
    }
    out[oE + rank] = v;
  }
}

// ======================= launch =================================================
extern "C" void kernel_launch(void* const* d_in, const int* in_sizes, int n_in,
                              void* d_out, int out_size) {
  const float* omega  = (const float*)d_in[0];
  const float* Phi    = (const float*)d_in[1];
  const float* metric = (const float*)d_in[2];
  int n = in_sizes[2] / 49;
  if (n > NMAX) n = NMAX;

  float* out = (float*)d_out;
  int oE = out_size - 77;
  int oM = oE - 77 * 77;
  int writeY = (out_size >= 33957 + 77 * 77 + 77) ? 1 : 0;

  k_weights<<<1, 1024>>>(metric, n);

  int chunk = (n + NCHK - 1) / NCHK;
  size_t smMain = (size_t)(35 * 256 + 35 * PH_LD + 448) * sizeof(float);
  k_main<<<NGRID, 256, smMain>>>(omega, Phi, n, chunk);

  k_reduceY<<<(441 * 77 + 255) / 256, 256>>>(out, writeY);

  size_t smEig = (size_t)(NPAIR * NK + 77 * ALD) * sizeof(float);
  cudaFuncSetAttribute(k_meig, cudaFuncAttributeMaxDynamicSharedMemorySize,
                       (int)smEig);
  k_meig<<<1, 1024, smEig>>>(out, oM, oE);
}

// round 4
// speedup vs baseline: 2.1560x; 1.2807x over previous
#include <cuda_runtime.h>
#include <math.h>

// ======================= compile-time structure constants =======================
struct Tables {
  signed char   ta[35][6];
  signed char   tb[35][6];
  float         ts[35][6];
  unsigned char p2i[256];
  unsigned char p2j[256];
};

constexpr Tables makeTables() {
  Tables T{};
  int c = 0;
  for (int x = 0; x < 7; x++)
    for (int y = x + 1; y < 7; y++)
      for (int z = y + 1; z < 7; z++) {
        int comp[4] = {0, 0, 0, 0};
        int m = 0;
        for (int e = 0; e < 7; e++)
          if (e != x && e != y && e != z) comp[m++] = e;
        int t = 0;
        for (int u = 0; u < 4; u++)
          for (int v = u + 1; v < 4; v++) {
            int a0 = comp[u], a1 = comp[v];
            int b0 = -1, b1 = -1;
            for (int e = 0; e < 4; e++) {
              if (e != u && e != v) { if (b0 < 0) b0 = comp[e]; else b1 = comp[e]; }
            }
            int perm[7] = {a0, a1, b0, b1, x, y, z};
            int inv = 0;
            for (int q = 0; q < 7; q++)
              for (int r = q + 1; r < 7; r++)
                if (perm[q] > perm[r]) inv++;
            T.ts[c][t] = (inv & 1) ? -1.0f : 1.0f;
            T.ta[c][t] = (signed char)(6 * a0 - a0 * (a0 - 1) / 2 + (a1 - a0 - 1));
            T.tb[c][t] = (signed char)(6 * b0 - b0 * (b0 - 1) / 2 + (b1 - b0 - 1));
            t++;
          }
        c++;
      }
  int p = 0;
  for (int i = 0; i < 21; i++)
    for (int j = i; j < 21; j++) {
      T.p2i[p] = (unsigned char)i;
      T.p2j[p] = (unsigned char)j;
      p++;
    }
  for (; p < 256; p++) { T.p2i[p] = 0; T.p2j[p] = 0; }
  return T;
}

constexpr Tables hT = makeTables();
__constant__ Tables dT = makeTables();

// ======================= device scratch =========================================
#define NMAX   4096
#define NCHK   148
#define NGRID  296
#define NPAIR  231
#define NK     77
#define PH_LD  82
#define TLD    79    // tridiag smem leading dim (odd)

__device__ float g_w[NMAX];
__device__ float g_part[NGRID][128 * 80];
__device__ float g_S[NPAIR * NK];
__device__ float g_A[NK * NK];
__device__ float g_d[NK];
__device__ float g_e[NK];

// ======================= f32x2 packed-FMA helpers ===============================
__device__ __forceinline__ unsigned long long pack2(float x) {
  unsigned long long r;
  asm("mov.b64 %0, {%1, %1};" : "=l"(r) : "f"(x));
  return r;
}
__device__ __forceinline__ void ffma2(unsigned long long &d, unsigned long long a,
                                      unsigned long long b) {
  asm("fma.rn.f32x2 %0, %1, %2, %0;" : "+l"(d) : "l"(a), "l"(b));
}
__device__ __forceinline__ float2 unpack2(unsigned long long v) {
  float2 f;
  asm("mov.b64 {%0, %1}, %2;" : "=f"(f.x), "=f"(f.y) : "l"(v));
  return f;
}

// ======================= kernel 1: Monte-Carlo weights ==========================
__global__ void __launch_bounds__(1024, 1)
k_weights(const float* __restrict__ metric, int n) {
  __shared__ float red[1024];
  __shared__ float invsum;
  float local = 0.f;
  for (int idx = threadIdx.x; idx < n; idx += 1024) {
    float a[7][7];
#pragma unroll
    for (int r = 0; r < 7; r++)
#pragma unroll
      for (int cc = 0; cc < 7; cc++) a[r][cc] = metric[idx * 49 + r * 7 + cc];
    float det = 1.f;
    for (int k = 0; k < 7; k++) {
      int piv = k;
      float mx = fabsf(a[k][k]);
      for (int r = k + 1; r < 7; r++) {
        float v = fabsf(a[r][k]);
        if (v > mx) { mx = v; piv = r; }
      }
      if (piv != k) {
        det = -det;
        for (int cc = 0; cc < 7; cc++) {
          float tmp = a[k][cc]; a[k][cc] = a[piv][cc]; a[piv][cc] = tmp;
        }
      }
      float akk = a[k][k];
      det *= akk;
      float inv = (akk != 0.f) ? 1.f / akk : 0.f;
      for (int r = k + 1; r < 7; r++) {
        float f = a[r][k] * inv;
        for (int cc = k + 1; cc < 7; cc++) a[r][cc] -= f * a[k][cc];
      }
    }
    float vol = sqrtf(fabsf(det));
    g_w[idx] = vol;
    local += vol;
  }
  red[threadIdx.x] = local;
  __syncthreads();
  for (int s = 512; s > 0; s >>= 1) {
    if (threadIdx.x < s) red[threadIdx.x] += red[threadIdx.x + s];
    __syncthreads();
  }
  if (threadIdx.x == 0) invsum = 1.f / red[0];
  __syncthreads();
  for (int idx = threadIdx.x; idx < n; idx += 1024) g_w[idx] *= invsum;
}

// ======================= D-compute: fully unrolled ==============================
template <int C, int T>
__device__ __forceinline__ float dterms(const float (&wi)[21], const float (&wj)[21],
                                        float acc) {
  constexpr int a = hT.ta[C][T];
  constexpr int b = hT.tb[C][T];
  if constexpr (hT.ts[C][T] > 0.f)
    acc = fmaf(wi[a], wj[b], acc);
  else
    acc = fmaf(-wi[a], wj[b], acc);
  if constexpr (T + 1 < 6) return dterms<C, T + 1>(wi, wj, acc);
  return acc;
}

template <int C>
__device__ __forceinline__ void dAll(float* Ds, int tid, const float (&wi)[21],
                                     const float (&wj)[21]) {
  Ds[C * 256 + tid] = dterms<C, 0>(wi, wj, 0.0f);
  if constexpr (C + 1 < 35) dAll<C + 1>(Ds, tid, wi, wj);
}

// ======================= kernel 2: fused D + big contraction ====================
__global__ void __launch_bounds__(256, 2)
k_main(const float* __restrict__ omega, const float* __restrict__ Phi, int n,
       int chunk) {
  extern __shared__ float sm[];
  float* Ds  = sm;
  float* Phs = sm + 35 * 256;
  float* Ws  = sm + 35 * 256 + 35 * PH_LD;

  const int tid   = threadIdx.x;
  const int lane  = tid & 31;
  const int warp  = tid >> 5;
  const int h     = blockIdx.x & 1;
  const int nc    = blockIdx.x >> 1;
  const int pbase = h * 128 + lane * 4;
  const int kbase = warp * 10;
  const int pi = dT.p2i[tid];
  const int pj = dT.p2j[tid];

  int phAddr[11];
#pragma unroll
  for (int j = 0; j < 11; j++) {
    int idx = tid + j * 256;
    int k = idx / 35;
    int c = idx - k * 35;
    phAddr[j] = c * PH_LD + k;
  }

  if (tid < 35 * 5) {
    int c = tid / 5, r = tid - c * 5;
    Phs[c * PH_LD + 77 + r] = 0.f;
  }

  unsigned long long acc[4][5];
#pragma unroll
  for (int a = 0; a < 4; a++)
#pragma unroll
    for (int b = 0; b < 5; b++) acc[a][b] = 0ull;

  int n0 = nc * chunk;
  int n1 = n0 + chunk;
  if (n1 > n) n1 = n;

  float rO0 = 0.f, rO1 = 0.f, rP[11];
#pragma unroll
  for (int j = 0; j < 11; j++) rP[j] = 0.f;

  if (n0 < n1) {
    const float* og = omega + (size_t)n0 * 441;
    rO0 = og[tid];
    if (tid + 256 < 441) rO1 = og[tid + 256];
    const float* pg = Phi + (size_t)n0 * 2695;
#pragma unroll
    for (int j = 0; j < 11; j++) {
      int idx = tid + j * 256;
      if (idx < 2695) rP[j] = pg[idx];
    }
  }

  for (int nn = n0; nn < n1; nn++) {
    const float wn = g_w[nn];
    __syncthreads();
    Ws[tid] = rO0;
    if (tid + 256 < 441) Ws[tid + 256] = rO1;
#pragma unroll
    for (int j = 0; j < 11; j++) {
      int idx = tid + j * 256;
      if (idx < 2695) Phs[phAddr[j]] = rP[j] * wn;
    }
    __syncthreads();

    {
      int nx = (nn + 1 < n1) ? nn + 1 : nn;
      const float* og = omega + (size_t)nx * 441;
      rO0 = og[tid];
      if (tid + 256 < 441) rO1 = og[tid + 256];
      const float* pg = Phi + (size_t)nx * 2695;
#pragma unroll
      for (int j = 0; j < 11; j++) {
        int idx = tid + j * 256;
        if (idx < 2695) rP[j] = pg[idx];
      }
    }

    {
      float wi[21], wj[21];
      const float* Wi = &Ws[pi * 21];
      const float* Wj = &Ws[pj * 21];
#pragma unroll
      for (int a = 0; a < 21; a++) { wi[a] = Wi[a]; wj[a] = Wj[a]; }
      dAll<0>(Ds, tid, wi, wj);
    }
    __syncthreads();

#pragma unroll 1
    for (int c = 0; c < 35; c++) {
      const float4 d0 = *(const float4*)&Ds[c * 256 + pbase];
      unsigned long long dd[4];
      dd[0] = pack2(d0.x); dd[1] = pack2(d0.y);
      dd[2] = pack2(d0.z); dd[3] = pack2(d0.w);
      unsigned long long ph[5];
#pragma unroll
      for (int u = 0; u < 5; u++)
        ph[u] = *(const unsigned long long*)&Phs[c * PH_LD + kbase + 2 * u];
#pragma unroll
      for (int p = 0; p < 4; p++)
#pragma unroll
        for (int u = 0; u < 5; u++) ffma2(acc[p][u], dd[p], ph[u]);
    }
  }

  float* outp = g_part[blockIdx.x];
#pragma unroll
  for (int p = 0; p < 4; p++)
#pragma unroll
    for (int u = 0; u < 5; u++) {
      float2 f = unpack2(acc[p][u]);
      *(float2*)&outp[(lane * 4 + p) * 80 + kbase + 2 * u] = f;
    }
}

// ======================= kernel 3: reduce partials, emit Y ======================
__global__ void k_reduceY(float* __restrict__ out, int writeY) {
  int idx = blockIdx.x * blockDim.x + threadIdx.x;
  if (idx >= 441 * 77) return;
  int i = idx / 1617;
  int rem = idx - i * 1617;
  int j = rem / 77;
  int k = rem - j * 77;
  int lo = i < j ? i : j;
  int hi = i < j ? j : i;
  int p = lo * 21 - lo * (lo - 1) / 2 + (hi - lo);
  int hh = p >> 7;
  int lp = p & 127;
  float s = 0.f;
#pragma unroll 4
  for (int b = 0; b < NCHK; b++) s += g_part[2 * b + hh][lp * 80 + k];
  if (writeY) out[idx] = (j >= i) ? s : -s;
  if (i <= j) g_S[p * 77 + k] = s;
}

// ======================= kernel 4: build M = S^T diag(m) S ======================
// grid 77 (one block per row k), 128 threads.
__global__ void __launch_bounds__(128, 1)
k_buildM(float* __restrict__ out, int oM) {
  __shared__ float cs[NPAIR];
  const int k = blockIdx.x;
  const int tid = threadIdx.x;
  for (int p = tid; p < NPAIR; p += 128) {
    float wgt = (dT.p2i[p] == dT.p2j[p]) ? 1.f : 2.f;
    cs[p] = wgt * g_S[p * 77 + k];
  }
  __syncthreads();
  if (tid < 77) {
    float a0 = 0.f, a1 = 0.f, a2 = 0.f, a3 = 0.f;
    int p = 0;
#pragma unroll 4
    for (; p + 4 <= NPAIR; p += 4) {
      a0 = fmaf(cs[p],     g_S[p * 77 + tid],       a0);
      a1 = fmaf(cs[p + 1], g_S[(p + 1) * 77 + tid], a1);
      a2 = fmaf(cs[p + 2], g_S[(p + 2) * 77 + tid], a2);
      a3 = fmaf(cs[p + 3], g_S[(p + 3) * 77 + tid], a3);
    }
    for (; p < NPAIR; p++) a0 = fmaf(cs[p], g_S[p * 77 + tid], a0);
    float v = (a0 + a1) + (a2 + a3);
    out[oM + k * 77 + tid] = v;
    g_A[k * 77 + tid] = v;
  }
}

// ======================= kernel 5: Householder tridiagonalization ===============
__device__ __forceinline__ float blockReduce256(float v, volatile float* red,
                                                int tid) {
  __syncthreads();  // protect red[] from previous use
#pragma unroll
  for (int o = 16; o; o >>= 1) v += __shfl_down_sync(0xffffffffu, v, o);
  if ((tid & 31) == 0) red[tid >> 5] = v;
  __syncthreads();
  if (tid < 8) {
    float r = red[tid];
#pragma unroll
    for (int o = 4; o; o >>= 1) r += __shfl_down_sync(0xffu, r, o);
    if (tid == 0) red[0] = r;
  }
  __syncthreads();
  return red[0];
}

__global__ void __launch_bounds__(256, 1) k_tridiag() {
  __shared__ float A[NK * TLD];
  __shared__ float us[80], ps[80];
  __shared__ float red[8];
  __shared__ float dd[NK], ee[NK];
  __shared__ float scA, scTb;
  __shared__ int   skip;
  const int tid = threadIdx.x;

  for (int idx = tid; idx < NK * NK; idx += 256) {
    int r = idx / NK, c = idx - r * NK;
    A[r * TLD + c] = g_A[idx];
  }
  __syncthreads();

#pragma unroll 1
  for (int k = 0; k < 75; k++) {
    const int m = 76 - k;
    float v = 0.f;
    if (tid < m) v = A[(k + 1 + tid) * TLD + k];
    float sigma = blockReduce256(v * v, red, tid);
    if (tid == 0) {
      dd[k] = A[k * TLD + k];
      if (sigma < 1e-30f) {
        ee[k] = 0.f;
        skip = 1;
      } else {
        float v0 = A[(k + 1) * TLD + k];
        float alpha = -copysignf(sqrtf(sigma), v0);
        ee[k] = alpha;
        scA = alpha;
        float beta = 2.f * (sigma - v0 * alpha);
        scTb = 2.f / beta;
        skip = 0;
      }
    }
    __syncthreads();
    if (skip) continue;

    if (tid < m) us[tid] = (tid == 0) ? v - scA : v;
    __syncthreads();

    float p = 0.f;
    if (tid < m) {
      const float* row = &A[(k + 1 + tid) * TLD + (k + 1)];
      float a0 = 0.f, a1 = 0.f, a2 = 0.f, a3 = 0.f;
      int j = 0;
      for (; j + 4 <= m; j += 4) {
        a0 = fmaf(row[j],     us[j],     a0);
        a1 = fmaf(row[j + 1], us[j + 1], a1);
        a2 = fmaf(row[j + 2], us[j + 2], a2);
        a3 = fmaf(row[j + 3], us[j + 3], a3);
      }
      for (; j < m; j++) a0 = fmaf(row[j], us[j], a0);
      p = ((a0 + a1) + (a2 + a3)) * scTb;
    }
    float upT = blockReduce256((tid < m) ? p * us[tid] : 0.f, red, tid);
    if (tid < m) ps[tid] = p - (upT * scTb * 0.5f) * us[tid];
    __syncthreads();

    for (int idx = tid; idx < m * m; idx += 256) {
      int i = idx / m, j = idx - i * m;
      A[(k + 1 + i) * TLD + (k + 1 + j)] -= us[i] * ps[j] + ps[i] * us[j];
    }
    __syncthreads();
  }

  if (tid == 0) {
    dd[75] = A[75 * TLD + 75];
    ee[75] = A[76 * TLD + 75];
    dd[76] = A[76 * TLD + 76];
    ee[76] = 0.f;
  }
  __syncthreads();
  if (tid < NK) {
    g_d[tid] = dd[tid];
    g_e[tid] = ee[tid];
  }
}

// ======================= kernel 6: Sturm multisection eigenvalues ===============
#define NPROBE 13
#define NROUND 12

__global__ void __launch_bounds__(1024, 1)
k_bisect(float* __restrict__ out, int oE) {
  __shared__ float d_s[NK], e2_s[NK];
  __shared__ float lo_s[NK], hi_s[NK];
  __shared__ float xs[NK * NPROBE];
  __shared__ int   cs[NK * NPROBE];
  __shared__ float gl_s, gh_s, piv_s;
  const int tid = threadIdx.x;
  const int g = tid / NPROBE;      // eigenvalue group (ascending index)
  const int j = tid - g * NPROBE;  // probe id
  const bool act = (g < NK);

  if (tid < NK) {
    d_s[tid] = g_d[tid];
    float e = g_e[tid];
    e2_s[tid] = e * e;
  }
  __syncthreads();

  if (tid == 0) {
    float gl = 3.4e38f, gh = -3.4e38f, me2 = 0.f;
    for (int i = 0; i < NK; i++) {
      float eprev = (i > 0) ? sqrtf(e2_s[i - 1]) : 0.f;
      float ecur  = (i < 76) ? sqrtf(e2_s[i]) : 0.f;
      float r = eprev + ecur;
      gl = fminf(gl, d_s[i] - r);
      gh = fmaxf(gh, d_s[i] + r);
      me2 = fmaxf(me2, e2_s[i]);
    }
    float wid = fmaxf(gh - gl, 1e-20f);
    gl_s = gl - 1e-3f * wid;
    gh_s = gh + 1e-3f * wid;
    piv_s = fmaxf(me2 * 1.2e-38f, 1e-37f);
  }
  __syncthreads();
  if (tid < NK) { lo_s[tid] = gl_s; hi_s[tid] = gh_s; }
  __syncthreads();

  const float pivmin = piv_s;
  const float cj = (float)(j + 1) / (float)(NPROBE + 1);

#pragma unroll 1
  for (int r = 0; r < NROUND; r++) {
    if (act) {
      float lo = lo_s[g], hi = hi_s[g];
      float x = lo + (hi - lo) * cj;
      xs[tid] = x;
      // Sturm count: # eigenvalues < x
      float q = d_s[0] - x;
      int cnt = (q < 0.f);
#pragma unroll 4
      for (int i = 1; i < NK; i++) {
        float aq = fabsf(q);
        if (aq < pivmin) q = -pivmin;
        q = d_s[i] - x - __fdividef(e2_s[i - 1], q);
        cnt += (q < 0.f);
      }
      cs[tid] = cnt;
    }
    __syncthreads();
    if (act && j == 0) {
      float lo = lo_s[g], hi = hi_s[g];
      for (int jj = 0; jj < NPROBE; jj++) {
        int c = cs[g * NPROBE + jj];
        float x = xs[g * NPROBE + jj];
        if (c <= g) lo = x;
        else { hi = x; break; }
      }
      lo_s[g] = lo;
      hi_s[g] = hi;
    }
    __syncthreads();
  }

  if (act && j == 0) out[oE + (76 - g)] = 0.5f * (lo_s[g] + hi_s[g]);
}

// ======================= launch =================================================
extern "C" void kernel_launch(void* const* d_in, const int* in_sizes, int n_in,
                              void* d_out, int out_size) {
  const float* omega  = (const float*)d_in[0];
  const float* Phi    = (const float*)d_in[1];
  const float* metric = (const float*)d_in[2];
  int n = in_sizes[2] / 49;
  if (n > NMAX) n = NMAX;

  float* out = (float*)d_out;
  int oE = out_size - 77;
  int oM = oE - 77 * 77;
  int writeY = (out_size >= 33957 + 77 * 77 + 77) ? 1 : 0;

  k_weights<<<1, 1024>>>(metric, n);

  int chunk = (n + NCHK - 1) / NCHK;
  size_t smMain = (size_t)(35 * 256 + 35 * PH_LD + 448) * sizeof(float);
  k_main<<<NGRID, 256, smMain>>>(omega, Phi, n, chunk);

  k_reduceY<<<(441 * 77 + 255) / 256, 256>>>(out, writeY);

  k_buildM<<<77, 128>>>(out, oM);
  k_tridiag<<<1, 256>>>();
  k_bisect<<<1, 1024>>>(out, oE);
}

// round 6
// speedup vs baseline: 2.4335x; 1.1287x over previous
#include <cuda_runtime.h>
#include <math.h>

// ======================= compile-time structure constants =======================
struct Tables {
  signed char   ta[35][6];
  signed char   tb[35][6];
  float         ts[35][6];
  unsigned char p2i[256];
  unsigned char p2j[256];
};

constexpr Tables makeTables() {
  Tables T{};
  int c = 0;
  for (int x = 0; x < 7; x++)
    for (int y = x + 1; y < 7; y++)
      for (int z = y + 1; z < 7; z++) {
        int comp[4] = {0, 0, 0, 0};
        int m = 0;
        for (int e = 0; e < 7; e++)
          if (e != x && e != y && e != z) comp[m++] = e;
        int t = 0;
        for (int u = 0; u < 4; u++)
          for (int v = u + 1; v < 4; v++) {
            int a0 = comp[u], a1 = comp[v];
            int b0 = -1, b1 = -1;
            for (int e = 0; e < 4; e++) {
              if (e != u && e != v) { if (b0 < 0) b0 = comp[e]; else b1 = comp[e]; }
            }
            int perm[7] = {a0, a1, b0, b1, x, y, z};
            int inv = 0;
            for (int q = 0; q < 7; q++)
              for (int r = q + 1; r < 7; r++)
                if (perm[q] > perm[r]) inv++;
            T.ts[c][t] = (inv & 1) ? -1.0f : 1.0f;
            T.ta[c][t] = (signed char)(6 * a0 - a0 * (a0 - 1) / 2 + (a1 - a0 - 1));
            T.tb[c][t] = (signed char)(6 * b0 - b0 * (b0 - 1) / 2 + (b1 - b0 - 1));
            t++;
          }
        c++;
      }
  int p = 0;
  for (int i = 0; i < 21; i++)
    for (int j = i; j < 21; j++) {
      T.p2i[p] = (unsigned char)i;
      T.p2j[p] = (unsigned char)j;
      p++;
    }
  for (; p < 256; p++) { T.p2i[p] = 0; T.p2j[p] = 0; }
  return T;
}

constexpr Tables hT = makeTables();
__constant__ Tables dT = makeTables();

// ======================= device scratch =========================================
#define NMAX   4096
#define NCHK   148
#define NGRID  296
#define NPAIR  231
#define NK     77
#define PH_LD  82
#define DS_LD  128
#define TLD    79

__device__ float g_w[NMAX];
__device__ float g_part[NGRID][128 * 80];
__device__ float g_S[NPAIR * NK];
__device__ float g_A[NK * NK];
__device__ float g_d[NK];
__device__ float g_e[NK];

// ======================= f32x2 packed-FMA helpers ===============================
__device__ __forceinline__ unsigned long long pack2(float x) {
  unsigned long long r;
  asm("mov.b64 %0, {%1, %1};" : "=l"(r) : "f"(x));
  return r;
}
__device__ __forceinline__ void ffma2(unsigned long long &d, unsigned long long a,
                                      unsigned long long b) {
  asm("fma.rn.f32x2 %0, %1, %2, %0;" : "+l"(d) : "l"(a), "l"(b));
}
__device__ __forceinline__ float2 unpack2(unsigned long long v) {
  float2 f;
  asm("mov.b64 {%0, %1}, %2;" : "=f"(f.x), "=f"(f.y) : "l"(v));
  return f;
}

// ======================= kernel 1: Monte-Carlo weights ==========================
__global__ void __launch_bounds__(1024, 1)
k_weights(const float* __restrict__ metric, int n) {
  __shared__ float red[1024];
  __shared__ float invsum;
  float local = 0.f;
  for (int idx = threadIdx.x; idx < n; idx += 1024) {
    float a[7][7];
#pragma unroll
    for (int r = 0; r < 7; r++)
#pragma unroll
      for (int cc = 0; cc < 7; cc++) a[r][cc] = metric[idx * 49 + r * 7 + cc];
    float det = 1.f;
    for (int k = 0; k < 7; k++) {
      int piv = k;
      float mx = fabsf(a[k][k]);
      for (int r = k + 1; r < 7; r++) {
        float v = fabsf(a[r][k]);
        if (v > mx) { mx = v; piv = r; }
      }
      if (piv != k) {
        det = -det;
        for (int cc = 0; cc < 7; cc++) {
          float tmp = a[k][cc]; a[k][cc] = a[piv][cc]; a[piv][cc] = tmp;
        }
      }
      float akk = a[k][k];
      det *= akk;
      float inv = (akk != 0.f) ? 1.f / akk : 0.f;
      for (int r = k + 1; r < 7; r++) {
        float f = a[r][k] * inv;
        for (int cc = k + 1; cc < 7; cc++) a[r][cc] -= f * a[k][cc];
      }
    }
    float vol = sqrtf(fabsf(det));
    g_w[idx] = vol;
    local += vol;
  }
  red[threadIdx.x] = local;
  __syncthreads();
  for (int s = 512; s > 0; s >>= 1) {
    if (threadIdx.x < s) red[threadIdx.x] += red[threadIdx.x + s];
    __syncthreads();
  }
  if (threadIdx.x == 0) invsum = 1.f / red[0];
  __syncthreads();
  for (int idx = threadIdx.x; idx < n; idx += 1024) g_w[idx] *= invsum;
}

// ======================= D-compute: fully unrolled, c-range split ===============
template <int C, int T>
__device__ __forceinline__ float dterms(const float (&wi)[21], const float (&wj)[21],
                                        float acc) {
  constexpr int a = hT.ta[C][T];
  constexpr int b = hT.tb[C][T];
  if constexpr (hT.ts[C][T] > 0.f)
    acc = fmaf(wi[a], wj[b], acc);
  else
    acc = fmaf(-wi[a], wj[b], acc);
  if constexpr (T + 1 < 6) return dterms<C, T + 1>(wi, wj, acc);
  return acc;
}

template <int C, int CEND>
__device__ __forceinline__ void dRange(float* Ds, int local, const float (&wi)[21],
                                       const float (&wj)[21]) {
  Ds[C * DS_LD + local] = dterms<C, 0>(wi, wj, 0.0f);
  if constexpr (C + 1 < CEND) dRange<C + 1, CEND>(Ds, local, wi, wj);
}

// ======================= kernel 2: fused D + big contraction ====================
__global__ void __launch_bounds__(256, 2)
k_main(const float* __restrict__ omega, const float* __restrict__ Phi, int n,
       int chunk) {
  extern __shared__ float sm[];
  float* Ds  = sm;
  float* Phs = sm + 35 * DS_LD;
  float* Ws  = sm + 35 * DS_LD + 35 * PH_LD;

  const int tid   = threadIdx.x;
  const int lane  = tid & 31;
  const int warp  = tid >> 5;
  const int h     = blockIdx.x & 1;
  const int nc    = blockIdx.x >> 1;
  const int lp4   = lane * 4;
  const int kbase = warp * 10;
  const int myLocal = tid & 127;
  const int myPair  = h * 128 + myLocal;
  const int pi = dT.p2i[myPair & 255];
  const int pj = dT.p2j[myPair & 255];

  int phAddr[11];
#pragma unroll
  for (int j = 0; j < 11; j++) {
    int idx = tid + j * 256;
    int k = idx / 35;
    int c = idx - k * 35;
    phAddr[j] = c * PH_LD + k;
  }

  if (tid < 35 * 5) {
    int c = tid / 5, r = tid - c * 5;
    Phs[c * PH_LD + 77 + r] = 0.f;
  }

  unsigned long long acc[4][5];
#pragma unroll
  for (int a = 0; a < 4; a++)
#pragma unroll
    for (int b = 0; b < 5; b++) acc[a][b] = 0ull;

  int n0 = nc * chunk;
  int n1 = n0 + chunk;
  if (n1 > n) n1 = n;

  float rO0 = 0.f, rO1 = 0.f, rP[11];
#pragma unroll
  for (int j = 0; j < 11; j++) rP[j] = 0.f;

  if (n0 < n1) {
    const float* og = omega + (size_t)n0 * 441;
    rO0 = og[tid];
    if (tid + 256 < 441) rO1 = og[tid + 256];
    const float* pg = Phi + (size_t)n0 * 2695;
#pragma unroll
    for (int j = 0; j < 11; j++) {
      int idx = tid + j * 256;
      if (idx < 2695) rP[j] = pg[idx];
    }
  }

  for (int nn = n0; nn < n1; nn++) {
    const float wn = g_w[nn];
    __syncthreads();
    Ws[tid] = rO0;
    if (tid + 256 < 441) Ws[tid + 256] = rO1;
#pragma unroll
    for (int j = 0; j < 11; j++) {
      int idx = tid + j * 256;
      if (idx < 2695) Phs[phAddr[j]] = rP[j] * wn;
    }
    __syncthreads();

    {
      int nx = (nn + 1 < n1) ? nn + 1 : nn;
      const float* og = omega + (size_t)nx * 441;
      rO0 = og[tid];
      if (tid + 256 < 441) rO1 = og[tid + 256];
      const float* pg = Phi + (size_t)nx * 2695;
#pragma unroll
      for (int j = 0; j < 11; j++) {
        int idx = tid + j * 256;
        if (idx < 2695) rP[j] = pg[idx];
      }
    }

    {
      float wi[21], wj[21];
      const float* Wi = &Ws[pi * 21];
      const float* Wj = &Ws[pj * 21];
#pragma unroll
      for (int a = 0; a < 21; a++) { wi[a] = Wi[a]; wj[a] = Wj[a]; }
      if (tid < 128)
        dRange<0, 18>(Ds, myLocal, wi, wj);
      else
        dRange<18, 35>(Ds, myLocal, wi, wj);
    }
    __syncthreads();

#pragma unroll 1
    for (int c = 0; c < 35; c++) {
      const float4 d0 = *(const float4*)&Ds[c * DS_LD + lp4];
      unsigned long long dd[4];
      dd[0] = pack2(d0.x); dd[1] = pack2(d0.y);
      dd[2] = pack2(d0.z); dd[3] = pack2(d0.w);
      unsigned long long ph[5];
#pragma unroll
      for (int u = 0; u < 5; u++)
        ph[u] = *(const unsigned long long*)&Phs[c * PH_LD + kbase + 2 * u];
#pragma unroll
      for (int p = 0; p < 4; p++)
#pragma unroll
        for (int u = 0; u < 5; u++) ffma2(acc[p][u], dd[p], ph[u]);
    }
  }

  float* outp = g_part[blockIdx.x];
#pragma unroll
  for (int p = 0; p < 4; p++)
#pragma unroll
    for (int u = 0; u < 5; u++) {
      float2 f = unpack2(acc[p][u]);
      *(float2*)&outp[(lp4 + p) * 80 + kbase + 2 * u] = f;
    }
}

// ======================= kernel 3: reduce partials, emit Y ======================
__global__ void k_reduceY(float* __restrict__ out, int writeY) {
  int idx = blockIdx.x * blockDim.x + threadIdx.x;
  if (idx >= 441 * 77) return;
  int i = idx / 1617;
  int rem = idx - i * 1617;
  int j = rem / 77;
  int k = rem - j * 77;
  int lo = i < j ? i : j;
  int hi = i < j ? j : i;
  int p = lo * 21 - lo * (lo - 1) / 2 + (hi - lo);
  int hh = p >> 7;
  int lp = p & 127;
  float s = 0.f;
#pragma unroll 4
  for (int b = 0; b < NCHK; b++) s += g_part[2 * b + hh][lp * 80 + k];
  if (writeY) out[idx] = (j >= i) ? s : -s;
  if (i <= j) g_S[p * 77 + k] = s;
}

// ======================= kernel 4: build M = S^T diag(m) S ======================
__global__ void __launch_bounds__(128, 1)
k_buildM(float* __restrict__ out, int oM) {
  __shared__ float cs[NPAIR];
  const int k = blockIdx.x;
  const int tid = threadIdx.x;
  for (int p = tid; p < NPAIR; p += 128) {
    float wgt = (dT.p2i[p] == dT.p2j[p]) ? 1.f : 2.f;
    cs[p] = wgt * g_S[p * 77 + k];
  }
  __syncthreads();
  if (tid < 77) {
    float a0 = 0.f, a1 = 0.f, a2 = 0.f, a3 = 0.f;
    int p = 0;
#pragma unroll 4
    for (; p + 4 <= NPAIR; p += 4) {
      a0 = fmaf(cs[p],     g_S[p * 77 + tid],       a0);
      a1 = fmaf(cs[p + 1], g_S[(p + 1) * 77 + tid], a1);
      a2 = fmaf(cs[p + 2], g_S[(p + 2) * 77 + tid], a2);
      a3 = fmaf(cs[p + 3], g_S[(p + 3) * 77 + tid], a3);
    }
    for (; p < NPAIR; p++) a0 = fmaf(cs[p], g_S[p * 77 + tid], a0);
    float v = (a0 + a1) + (a2 + a3);
    out[oM + k * 77 + tid] = v;
    g_A[k * 77 + tid] = v;
  }
}

// ======================= kernel 5: Householder tridiagonalization ===============
__device__ __forceinline__ float blockReduce256(float v, volatile float* red,
                                                int tid) {
  __syncthreads();
#pragma unroll
  for (int o = 16; o; o >>= 1) v += __shfl_down_sync(0xffffffffu, v, o);
  if ((tid & 31) == 0) red[tid >> 5] = v;
  __syncthreads();
  if (tid < 8) {
    float r = red[tid];
#pragma unroll
    for (int o = 4; o; o >>= 1) r += __shfl_down_sync(0xffu, r, o);
    if (tid == 0) red[0] = r;
  }
  __syncthreads();
  return red[0];
}

__global__ void __launch_bounds__(256, 1) k_tridiag() {
  __shared__ float A[NK * TLD];
  __shared__ float us[80], ps[80], pp[80];
  __shared__ float red[8];
  __shared__ float dd[NK], ee[NK];
  __shared__ float scA, scTb;
  __shared__ int   skip;
  const int tid  = threadIdx.x;
  const int lane = tid & 31;
  const int warp = tid >> 5;
  const int rrow = tid >> 1;
  const int rq   = tid & 1;

  for (int idx = tid; idx < NK * NK; idx += 256) {
    int r = idx / NK, c = idx - r * NK;
    A[r * TLD + c] = g_A[idx];
  }
  __syncthreads();

#pragma unroll 1
  for (int k = 0; k < 75; k++) {
    const int m = 76 - k;
    float v = 0.f;
    if (tid < m) v = A[(k + 1 + tid) * TLD + k];
    float sigma = blockReduce256(v * v, red, tid);
    if (tid == 0) {
      dd[k] = A[k * TLD + k];
      if (sigma < 1e-30f) {
        ee[k] = 0.f;
        skip = 1;
      } else {
        float v0 = A[(k + 1) * TLD + k];
        float alpha = -copysignf(sqrtf(sigma), v0);
        ee[k] = alpha;
        scA = alpha;
        float beta = 2.f * (sigma - v0 * alpha);
        scTb = 2.f / beta;
        skip = 0;
      }
    }
    __syncthreads();
    if (skip) continue;

    if (tid < m) us[tid] = (tid == 0) ? v - scA : v;
    __syncthreads();

    // matvec p = scTb * A(sub) * u : 2 threads per row, shuffle-combined
    {
      float a0 = 0.f, a1 = 0.f, a2 = 0.f, a3 = 0.f;
      if (rrow < m) {
        const float* row = &A[(k + 1 + rrow) * TLD + (k + 1)];
        int j = rq;
        for (; j + 6 < m; j += 8) {
          a0 = fmaf(row[j],     us[j],     a0);
          a1 = fmaf(row[j + 2], us[j + 2], a1);
          a2 = fmaf(row[j + 4], us[j + 4], a2);
          a3 = fmaf(row[j + 6], us[j + 6], a3);
        }
        for (; j < m; j += 2) a0 = fmaf(row[j], us[j], a0);
      }
      float s = (a0 + a1) + (a2 + a3);
      s += __shfl_xor_sync(0xffffffffu, s, 1);
      if (rrow < m && rq == 0) pp[rrow] = s * scTb;
    }
    __syncthreads();   // pp[] visible to all before cross-thread read (R5 race fix)
    float upT = blockReduce256((tid < m) ? pp[tid] * us[tid] : 0.f, red, tid);
    if (tid < m) ps[tid] = pp[tid] - (upT * scTb * 0.5f) * us[tid];
    __syncthreads();

    // rank-2 update, division-free: warp per row, lane per column
    for (int i = warp; i < m; i += 8) {
      const float ui = us[i], pi_ = ps[i];
      float* rowA = &A[(k + 1 + i) * TLD + (k + 1)];
      for (int j = lane; j < m; j += 32)
        rowA[j] -= ui * ps[j] + pi_ * us[j];
    }
    __syncthreads();
  }

  if (tid == 0) {
    dd[75] = A[75 * TLD + 75];
    ee[75] = A[76 * TLD + 75];
    dd[76] = A[76 * TLD + 76];
    ee[76] = 0.f;
  }
  __syncthreads();
  if (tid < NK) {
    g_d[tid] = dd[tid];
    g_e[tid] = ee[tid];
  }
}

// ======================= kernel 6: Sturm multisection eigenvalues ===============
#define NPROBE 13
#define NROUND 10

__global__ void __launch_bounds__(1024, 1)
k_bisect(float* __restrict__ out, int oE) {
  __shared__ float d_s[NK], e2_s[NK];
  __shared__ float lo_s[NK], hi_s[NK];
  __shared__ float xs[NK * NPROBE];
  __shared__ int   cs[NK * NPROBE];
  __shared__ float gl_s, gh_s, piv_s;
  const int tid = threadIdx.x;
  const int g = tid / NPROBE;
  const int j = tid - g * NPROBE;
  const bool act = (g < NK);

  if (tid < NK) {
    d_s[tid] = g_d[tid];
    float e = g_e[tid];
    e2_s[tid] = e * e;
  }
  __syncthreads();

  if (tid == 0) {
    float gl = 3.4e38f, gh = -3.4e38f, me2 = 0.f;
    for (int i = 0; i < NK; i++) {
      float eprev = (i > 0) ? sqrtf(e2_s[i - 1]) : 0.f;
      float ecur  = (i < 76) ? sqrtf(e2_s[i]) : 0.f;
      float r = eprev + ecur;
      gl = fminf(gl, d_s[i] - r);
      gh = fmaxf(gh, d_s[i] + r);
      me2 = fmaxf(me2, e2_s[i]);
    }
    float wid = fmaxf(gh - gl, 1e-20f);
    gl_s = gl - 1e-3f * wid;
    gh_s = gh + 1e-3f * wid;
    piv_s = fmaxf(me2 * 1.2e-38f, 1e-37f);
  }
  __syncthreads();
  if (tid < NK) { lo_s[tid] = gl_s; hi_s[tid] = gh_s; }
  __syncthreads();

  const float pivmin = piv_s;
  const float cj = (float)(j + 1) / (float)(NPROBE + 1);

#pragma unroll 1
  for (int r = 0; r < NROUND; r++) {
    if (act) {
      float lo = lo_s[g], hi = hi_s[g];
      float x = lo + (hi - lo) * cj;
      xs[tid] = x;
      float q = d_s[0] - x;
      int cnt = (q < 0.f);
#pragma unroll 4
      for (int i = 1; i < NK; i++) {
        float aq = fabsf(q);
        if (aq < pivmin) q = -pivmin;
        q = d_s[i] - x - __fdividef(e2_s[i - 1], q);
        cnt += (q < 0.f);
      }
      cs[tid] = cnt;
    }
    __syncthreads();
    if (act && j == 0) {
      float lo = lo_s[g], hi = hi_s[g];
      for (int jj = 0; jj < NPROBE; jj++) {
        int c = cs[g * NPROBE + jj];
        float x = xs[g * NPROBE + jj];
        if (c <= g) lo = x;
        else { hi = x; break; }
      }
      lo_s[g] = lo;
      hi_s[g] = hi;
    }
    __syncthreads();
  }

  if (act && j == 0) out[oE + (76 - g)] = 0.5f * (lo_s[g] + hi_s[g]);
}

// ======================= launch =================================================
extern "C" void kernel_launch(void* const* d_in, const int* in_sizes, int n_in,
                              void* d_out, int out_size) {
  const float* omega  = (const float*)d_in[0];
  const float* Phi    = (const float*)d_in[1];
  const float* metric = (const float*)d_in[2];
  int n = in_sizes[2] / 49;
  if (n > NMAX) n = NMAX;

  float* out = (float*)d_out;
  int oE = out_size - 77;
  int oM = oE - 77 * 77;
  int writeY = (out_size >= 33957 + 77 * 77 + 77) ? 1 : 0;

  k_weights<<<1, 1024>>>(metric, n);

  int chunk = (n + NCHK - 1) / NCHK;
  size_t smMain = (size_t)(35 * DS_LD + 35 * PH_LD + 448) * sizeof(float);
  k_main<<<NGRID, 256, smMain>>>(omega, Phi, n, chunk);

  k_reduceY<<<(441 * 77 + 255) / 256, 256>>>(out, writeY);

  k_buildM<<<77, 128>>>(out, oM);
  k_tridiag<<<1, 256>>>();
  k_bisect<<<1, 1024>>>(out, oE);
}

// round 7
// speedup vs baseline: 3.1426x; 1.2914x over previous
#include <cuda_runtime.h>
#include <math.h>

// ======================= compile-time structure constants =======================
struct Tables {
  signed char   ta[35][6];
  signed char   tb[35][6];
  float         ts[35][6];
  unsigned char p2i[256];
  unsigned char p2j[256];
};

constexpr Tables makeTables() {
  Tables T{};
  int c = 0;
  for (int x = 0; x < 7; x++)
    for (int y = x + 1; y < 7; y++)
      for (int z = y + 1; z < 7; z++) {
        int comp[4] = {0, 0, 0, 0};
        int m = 0;
        for (int e = 0; e < 7; e++)
          if (e != x && e != y && e != z) comp[m++] = e;
        int t = 0;
        for (int u = 0; u < 4; u++)
          for (int v = u + 1; v < 4; v++) {
            int a0 = comp[u], a1 = comp[v];
            int b0 = -1, b1 = -1;
            for (int e = 0; e < 4; e++) {
              if (e != u && e != v) { if (b0 < 0) b0 = comp[e]; else b1 = comp[e]; }
            }
            int perm[7] = {a0, a1, b0, b1, x, y, z};
            int inv = 0;
            for (int q = 0; q < 7; q++)
              for (int r = q + 1; r < 7; r++)
                if (perm[q] > perm[r]) inv++;
            T.ts[c][t] = (inv & 1) ? -1.0f : 1.0f;
            T.ta[c][t] = (signed char)(6 * a0 - a0 * (a0 - 1) / 2 + (a1 - a0 - 1));
            T.tb[c][t] = (signed char)(6 * b0 - b0 * (b0 - 1) / 2 + (b1 - b0 - 1));
            t++;
          }
        c++;
      }
  int p = 0;
  for (int i = 0; i < 21; i++)
    for (int j = i; j < 21; j++) {
      T.p2i[p] = (unsigned char)i;
      T.p2j[p] = (unsigned char)j;
      p++;
    }
  for (; p < 256; p++) { T.p2i[p] = 0; T.p2j[p] = 0; }
  return T;
}

constexpr Tables hT = makeTables();
__constant__ Tables dT = makeTables();

// ======================= device scratch =========================================
#define NMAX   4096
#define NGRID  148
#define NPAIR  231
#define NK     77
#define PH_LD  82
#define DS_LD  256
#define TLD    79

__device__ float g_w[NMAX];
__device__ float g_psum[64];
__device__ float g_invsum;
__device__ float g_part[NGRID][256 * 80];
__device__ float g_S[NPAIR * NK];
__device__ float g_A[NK * NK];
__device__ float g_d[NK];
__device__ float g_e[NK];

// ======================= f32x2 packed-FMA helpers ===============================
__device__ __forceinline__ unsigned long long pack2(float x) {
  unsigned long long r;
  asm("mov.b64 %0, {%1, %1};" : "=l"(r) : "f"(x));
  return r;
}
__device__ __forceinline__ void ffma2(unsigned long long &d, unsigned long long a,
                                      unsigned long long b) {
  asm("fma.rn.f32x2 %0, %1, %2, %0;" : "+l"(d) : "l"(a), "l"(b));
}
__device__ __forceinline__ float2 unpack2(unsigned long long v) {
  float2 f;
  asm("mov.b64 {%0, %1}, %2;" : "=f"(f.x), "=f"(f.y) : "l"(v));
  return f;
}

// ======================= kernel 1a: per-sample volumes (full chip) ==============
// Static-index pivoted LU: all array indices compile-time after unroll -> registers.
__global__ void __launch_bounds__(256, 1)
k_vols(const float* __restrict__ metric, int n) {
  __shared__ float red[256];
  const int tid = threadIdx.x;
  const int idx = blockIdx.x * 256 + tid;
  float vol = 0.f;
  if (idx < n) {
    float a[7][7];
#pragma unroll
    for (int r = 0; r < 7; r++)
#pragma unroll
      for (int cc = 0; cc < 7; cc++) a[r][cc] = metric[idx * 49 + r * 7 + cc];
    float det = 1.f;
#pragma unroll
    for (int k = 0; k < 7; k++) {
      float mx = fabsf(a[k][k]);
      int piv = k;
#pragma unroll
      for (int r = k + 1; r < 7; r++) {
        float v = fabsf(a[r][k]);
        if (v > mx) { mx = v; piv = r; }
      }
#pragma unroll
      for (int r = k + 1; r < 7; r++) {
        if (piv == r) {   // constant indices inside -> stays in registers
          det = -det;
#pragma unroll
          for (int cc = k; cc < 7; cc++) {
            float t = a[k][cc]; a[k][cc] = a[r][cc]; a[r][cc] = t;
          }
        }
      }
      float akk = a[k][k];
      det *= akk;
      float inv = (akk != 0.f) ? 1.f / akk : 0.f;
#pragma unroll
      for (int r = k + 1; r < 7; r++) {
        float f = a[r][k] * inv;
#pragma unroll
        for (int cc = k + 1; cc < 7; cc++) a[r][cc] = fmaf(-f, a[k][cc], a[r][cc]);
      }
    }
    vol = sqrtf(fabsf(det));
    g_w[idx] = vol;
  }
  red[tid] = vol;
  __syncthreads();
#pragma unroll
  for (int s = 128; s > 0; s >>= 1) {
    if (tid < s) red[tid] += red[tid + s];
    __syncthreads();
  }
  if (tid == 0) g_psum[blockIdx.x] = red[0];
}

// kernel 1b: deterministic fixed-order sum of partials
__global__ void k_sumw(int nb) {
  if (threadIdx.x == 0) {
    float s = 0.f;
    for (int i = 0; i < nb; i++) s += g_psum[i];
    g_invsum = 1.f / s;
  }
}

// ======================= D-compute: fully unrolled, c-range split ===============
template <int C, int T>
__device__ __forceinline__ float dterms(const float (&wi)[21], const float (&wj)[21],
                                        float acc) {
  constexpr int a = hT.ta[C][T];
  constexpr int b = hT.tb[C][T];
  if constexpr (hT.ts[C][T] > 0.f)
    acc = fmaf(wi[a], wj[b], acc);
  else
    acc = fmaf(-wi[a], wj[b], acc);
  if constexpr (T + 1 < 6) return dterms<C, T + 1>(wi, wj, acc);
  return acc;
}

template <int C, int CEND>
__device__ __forceinline__ void dRange(float* Ds, int local, const float (&wi)[21],
                                       const float (&wj)[21]) {
  Ds[C * DS_LD + local] = dterms<C, 0>(wi, wj, 0.0f);
  if constexpr (C + 1 < CEND) dRange<C + 1, CEND>(Ds, local, wi, wj);
}

// ======================= kernel 2: fused D + big contraction ====================
// grid 148 x 512 threads (one block/SM). Shared Phi/omega staging; warps 0-7
// own pairs 0-127, warps 8-15 own pairs 128-255; kbase = (warp&7)*10.
__global__ void __launch_bounds__(512, 1)
k_main(const float* __restrict__ omega, const float* __restrict__ Phi, int n,
       int chunk) {
  extern __shared__ float sm[];
  float* Ds  = sm;                             // [35][256]
  float* Phs = sm + 35 * DS_LD;                // [35][PH_LD]
  float* Ws  = sm + 35 * DS_LD + 35 * PH_LD;   // [441]

  const int tid   = threadIdx.x;
  const int lane  = tid & 31;
  const int warp  = tid >> 5;
  const int half  = warp >> 3;
  const int pbase = half * 128 + lane * 4;
  const int kbase = (warp & 7) * 10;
  const int myLocal = tid & 255;
  const int pi = dT.p2i[myLocal];
  const int pj = dT.p2j[myLocal];

  int phAddr[6];
#pragma unroll
  for (int j = 0; j < 6; j++) {
    int idx = tid + j * 512;
    int k = idx / 35;
    int c = idx - k * 35;
    phAddr[j] = c * PH_LD + k;
  }

  if (tid < 35 * 5) {
    int c = tid / 5, r = tid - c * 5;
    Phs[c * PH_LD + 77 + r] = 0.f;
  }

  unsigned long long acc[4][5];
#pragma unroll
  for (int a = 0; a < 4; a++)
#pragma unroll
    for (int b = 0; b < 5; b++) acc[a][b] = 0ull;

  int n0 = blockIdx.x * chunk;
  int n1 = n0 + chunk;
  if (n1 > n) n1 = n;

  float rO = 0.f, rP[6];
#pragma unroll
  for (int j = 0; j < 6; j++) rP[j] = 0.f;

  if (n0 < n1) {
    const float* og = omega + (size_t)n0 * 441;
    if (tid < 441) rO = og[tid];
    const float* pg = Phi + (size_t)n0 * 2695;
#pragma unroll
    for (int j = 0; j < 6; j++) {
      int idx = tid + j * 512;
      if (idx < 2695) rP[j] = pg[idx];
    }
  }

  for (int nn = n0; nn < n1; nn++) {
    const float wn = g_w[nn];
    __syncthreads();   // previous GEMM done reading smem
    if (tid < 441) Ws[tid] = rO;
#pragma unroll
    for (int j = 0; j < 6; j++) {
      int idx = tid + j * 512;
      if (idx < 2695) Phs[phAddr[j]] = rP[j] * wn;
    }
    __syncthreads();

    {  // prefetch next n
      int nx = (nn + 1 < n1) ? nn + 1 : nn;
      const float* og = omega + (size_t)nx * 441;
      if (tid < 441) rO = og[tid];
      const float* pg = Phi + (size_t)nx * 2695;
#pragma unroll
      for (int j = 0; j < 6; j++) {
        int idx = tid + j * 512;
        if (idx < 2695) rP[j] = pg[idx];
      }
    }

    {  // D phase: 512 threads, 256 local pairs, c split in half
      float wi[21], wj[21];
      const float* Wi = &Ws[pi * 21];
      const float* Wj = &Ws[pj * 21];
#pragma unroll
      for (int a = 0; a < 21; a++) { wi[a] = Wi[a]; wj[a] = Wj[a]; }
      if (tid < 256)
        dRange<0, 18>(Ds, myLocal, wi, wj);
      else
        dRange<18, 35>(Ds, myLocal, wi, wj);
    }
    __syncthreads();

#pragma unroll 5
    for (int c = 0; c < 35; c++) {
      const float4 d0 = *(const float4*)&Ds[c * DS_LD + pbase];
      unsigned long long dd[4];
      dd[0] = pack2(d0.x); dd[1] = pack2(d0.y);
      dd[2] = pack2(d0.z); dd[3] = pack2(d0.w);
      unsigned long long ph[5];
#pragma unroll
      for (int u = 0; u < 5; u++)
        ph[u] = *(const unsigned long long*)&Phs[c * PH_LD + kbase + 2 * u];
#pragma unroll
      for (int p = 0; p < 4; p++)
#pragma unroll
        for (int u = 0; u < 5; u++) ffma2(acc[p][u], dd[p], ph[u]);
    }
  }

  float* outp = g_part[blockIdx.x];
#pragma unroll
  for (int p = 0; p < 4; p++)
#pragma unroll
    for (int u = 0; u < 5; u++) {
      float2 f = unpack2(acc[p][u]);
      *(float2*)&outp[(pbase + p) * 80 + kbase + 2 * u] = f;
    }
}

// ======================= kernel 3: reduce partials, emit Y (scaled) =============
__global__ void k_reduceY(float* __restrict__ out, int writeY) {
  int idx = blockIdx.x * blockDim.x + threadIdx.x;
  if (idx >= 441 * 77) return;
  const float inv = g_invsum;
  int i = idx / 1617;
  int rem = idx - i * 1617;
  int j = rem / 77;
  int k = rem - j * 77;
  int lo = i < j ? i : j;
  int hi = i < j ? j : i;
  int p = lo * 21 - lo * (lo - 1) / 2 + (hi - lo);
  float s = 0.f;
#pragma unroll 4
  for (int b = 0; b < NGRID; b++) s += g_part[b][p * 80 + k];
  s *= inv;   // deferred Monte-Carlo normalization
  if (writeY) out[idx] = (j >= i) ? s : -s;
  if (i <= j) g_S[p * 77 + k] = s;
}

// ======================= kernel 4: build M = S^T diag(m) S ======================
__global__ void __launch_bounds__(128, 1)
k_buildM(float* __restrict__ out, int oM) {
  __shared__ float cs[NPAIR];
  const int k = blockIdx.x;
  const int tid = threadIdx.x;
  for (int p = tid; p < NPAIR; p += 128) {
    float wgt = (dT.p2i[p] == dT.p2j[p]) ? 1.f : 2.f;
    cs[p] = wgt * g_S[p * 77 + k];
  }
  __syncthreads();
  if (tid < 77) {
    float a0 = 0.f, a1 = 0.f, a2 = 0.f, a3 = 0.f;
    int p = 0;
#pragma unroll 4
    for (; p + 4 <= NPAIR; p += 4) {
      a0 = fmaf(cs[p],     g_S[p * 77 + tid],       a0);
      a1 = fmaf(cs[p + 1], g_S[(p + 1) * 77 + tid], a1);
      a2 = fmaf(cs[p + 2], g_S[(p + 2) * 77 + tid], a2);
      a3 = fmaf(cs[p + 3], g_S[(p + 3) * 77 + tid], a3);
    }
    for (; p < NPAIR; p++) a0 = fmaf(cs[p], g_S[p * 77 + tid], a0);
    float v = (a0 + a1) + (a2 + a3);
    out[oM + k * 77 + tid] = v;
    g_A[k * 77 + tid] = v;
  }
}

// ======================= kernel 5: Householder tridiagonalization ===============
__device__ __forceinline__ float blockReduce256(float v, volatile float* red,
                                                int tid) {
  __syncthreads();
#pragma unroll
  for (int o = 16; o; o >>= 1) v += __shfl_down_sync(0xffffffffu, v, o);
  if ((tid & 31) == 0) red[tid >> 5] = v;
  __syncthreads();
  if (tid < 8) {
    float r = red[tid];
#pragma unroll
    for (int o = 4; o; o >>= 1) r += __shfl_down_sync(0xffu, r, o);
    if (tid == 0) red[0] = r;
  }
  __syncthreads();
  return red[0];
}

__global__ void __launch_bounds__(256, 1) k_tridiag() {
  __shared__ float A[NK * TLD];
  __shared__ float us[80], ps[80], pp[80];
  __shared__ float red[8];
  __shared__ float dd[NK], ee[NK];
  __shared__ float scA, scTb;
  __shared__ int   skip;
  const int tid  = threadIdx.x;
  const int lane = tid & 31;
  const int warp = tid >> 5;
  const int rrow = tid >> 1;
  const int rq   = tid & 1;

  for (int idx = tid; idx < NK * NK; idx += 256) {
    int r = idx / NK, c = idx - r * NK;
    A[r * TLD + c] = g_A[idx];
  }
  __syncthreads();

#pragma unroll 1
  for (int k = 0; k < 75; k++) {
    const int m = 76 - k;
    float v = 0.f;
    if (tid < m) v = A[(k + 1 + tid) * TLD + k];
    float sigma = blockReduce256(v * v, red, tid);
    if (tid == 0) {
      dd[k] = A[k * TLD + k];
      if (sigma < 1e-30f) {
        ee[k] = 0.f;
        skip = 1;
      } else {
        float v0 = A[(k + 1) * TLD + k];
        float alpha = -copysignf(sqrtf(sigma), v0);
        ee[k] = alpha;
        scA = alpha;
        float beta = 2.f * (sigma - v0 * alpha);
        scTb = 2.f / beta;
        skip = 0;
      }
    }
    __syncthreads();
    if (skip) continue;

    if (tid < m) us[tid] = (tid == 0) ? v - scA : v;
    __syncthreads();

    {
      float a0 = 0.f, a1 = 0.f, a2 = 0.f, a3 = 0.f;
      if (rrow < m) {
        const float* row = &A[(k + 1 + rrow) * TLD + (k + 1)];
        int j = rq;
        for (; j + 6 < m; j += 8) {
          a0 = fmaf(row[j],     us[j],     a0);
          a1 = fmaf(row[j + 2], us[j + 2], a1);
          a2 = fmaf(row[j + 4], us[j + 4], a2);
          a3 = fmaf(row[j + 6], us[j + 6], a3);
        }
        for (; j < m; j += 2) a0 = fmaf(row[j], us[j], a0);
      }
      float s = (a0 + a1) + (a2 + a3);
      s += __shfl_xor_sync(0xffffffffu, s, 1);
      if (rrow < m && rq == 0) pp[rrow] = s * scTb;
    }
    __syncthreads();   // pp[] visible before cross-thread read
    float upT = blockReduce256((tid < m) ? pp[tid] * us[tid] : 0.f, red, tid);
    if (tid < m) ps[tid] = pp[tid] - (upT * scTb * 0.5f) * us[tid];
    __syncthreads();

    for (int i = warp; i < m; i += 8) {
      const float ui = us[i], pi_ = ps[i];
      float* rowA = &A[(k + 1 + i) * TLD + (k + 1)];
      for (int j = lane; j < m; j += 32)
        rowA[j] -= ui * ps[j] + pi_ * us[j];
    }
    __syncthreads();
  }

  if (tid == 0) {
    dd[75] = A[75 * TLD + 75];
    ee[75] = A[76 * TLD + 75];
    dd[76] = A[76 * TLD + 76];
    ee[76] = 0.f;
  }
  __syncthreads();
  if (tid < NK) {
    g_d[tid] = dd[tid];
    g_e[tid] = ee[tid];
  }
}

// ======================= kernel 6: Sturm multisection eigenvalues ===============
#define NPROBE 13
#define NROUND 10

__global__ void __launch_bounds__(1024, 1)
k_bisect(float* __restrict__ out, int oE) {
  __shared__ float d_s[NK], e2_s[NK];
  __shared__ float lo_s[NK], hi_s[NK];
  __shared__ float xs[NK * NPROBE];
  __shared__ int   cs[NK * NPROBE];
  __shared__ float gl_s, gh_s, piv_s;
  const int tid = threadIdx.x;
  const int g = tid / NPROBE;
  const int j = tid - g * NPROBE;
  const bool act = (g < NK);

  if (tid < NK) {
    d_s[tid] = g_d[tid];
    float e = g_e[tid];
    e2_s[tid] = e * e;
  }
  __syncthreads();

  if (tid == 0) {
    float gl = 3.4e38f, gh = -3.4e38f, me2 = 0.f;
    for (int i = 0; i < NK; i++) {
      float eprev = (i > 0) ? sqrtf(e2_s[i - 1]) : 0.f;
      float ecur  = (i < 76) ? sqrtf(e2_s[i]) : 0.f;
      float r = eprev + ecur;
      gl = fminf(gl, d_s[i] - r);
      gh = fmaxf(gh, d_s[i] + r);
      me2 = fmaxf(me2, e2_s[i]);
    }
    float wid = fmaxf(gh - gl, 1e-20f);
    gl_s = gl - 1e-3f * wid;
    gh_s = gh + 1e-3f * wid;
    piv_s = fmaxf(me2 * 1.2e-38f, 1e-37f);
  }
  __syncthreads();
  if (tid < NK) { lo_s[tid] = gl_s; hi_s[tid] = gh_s; }
  __syncthreads();

  const float pivmin = piv_s;
  const float cj = (float)(j + 1) / (float)(NPROBE + 1);

#pragma unroll 1
  for (int r = 0; r < NROUND; r++) {
    if (act) {
      float lo = lo_s[g], hi = hi_s[g];
      float x = lo + (hi - lo) * cj;
      xs[tid] = x;
      float q = d_s[0] - x;
      int cnt = (q < 0.f);
#pragma unroll 4
      for (int i = 1; i < NK; i++) {
        float aq = fabsf(q);
        if (aq < pivmin) q = -pivmin;
        q = d_s[i] - x - __fdividef(e2_s[i - 1], q);
        cnt += (q < 0.f);
      }
      cs[tid] = cnt;
    }
    __syncthreads();
    if (act && j == 0) {
      float lo = lo_s[g], hi = hi_s[g];
      for (int jj = 0; jj < NPROBE; jj++) {
        int c = cs[g * NPROBE + jj];
        float x = xs[g * NPROBE + jj];
        if (c <= g) lo = x;
        else { hi = x; break; }
      }
      lo_s[g] = lo;
      hi_s[g] = hi;
    }
    __syncthreads();
  }

  if (act && j == 0) out[oE + (76 - g)] = 0.5f * (lo_s[g] + hi_s[g]);
}

// ======================= launch =================================================
extern "C" void kernel_launch(void* const* d_in, const int* in_sizes, int n_in,
                              void* d_out, int out_size) {
  const float* omega  = (const float*)d_in[0];
  const float* Phi    = (const float*)d_in[1];
  const float* metric = (const float*)d_in[2];
  int n = in_sizes[2] / 49;
  if (n > NMAX) n = NMAX;

  float* out = (float*)d_out;
  int oE = out_size - 77;
  int oM = oE - 77 * 77;
  int writeY = (out_size >= 33957 + 77 * 77 + 77) ? 1 : 0;

  int nb = (n + 255) / 256;
  k_vols<<<nb, 256>>>(metric, n);
  k_sumw<<<1, 32>>>(nb);

  int chunk = (n + NGRID - 1) / NGRID;
  size_t smMain = (size_t)(35 * DS_LD + 35 * PH_LD + 441) * sizeof(float);
  cudaFuncSetAttribute(k_main, cudaFuncAttributeMaxDynamicSharedMemorySize,
                       (int)smMain);
  k_main<<<NGRID, 512, smMain>>>(omega, Phi, n, chunk);

  k_reduceY<<<(441 * 77 + 255) / 256, 256>>>(out, writeY);

  k_buildM<<<77, 128>>>(out, oM);
  k_tridiag<<<1, 256>>>();
  k_bisect<<<1, 1024>>>(out, oE);
}

// round 9
// speedup vs baseline: 3.6615x; 1.1651x over previous
#include <cuda_runtime.h>
#include <cuda_bf16.h>
#include <math.h>
#include <stdint.h>

// ======================= compile-time structure constants =======================
struct Tables {
  signed char   ta[35][6];
  signed char   tb[35][6];
  float         ts[35][6];
  unsigned char p2i[256];
  unsigned char p2j[256];
};

constexpr Tables makeTables() {
  Tables T{};
  int c = 0;
  for (int x = 0; x < 7; x++)
    for (int y = x + 1; y < 7; y++)
      for (int z = y + 1; z < 7; z++) {
        int comp[4] = {0, 0, 0, 0};
        int m = 0;
        for (int e = 0; e < 7; e++)
          if (e != x && e != y && e != z) comp[m++] = e;
        int t = 0;
        for (int u = 0; u < 4; u++)
          for (int v = u + 1; v < 4; v++) {
            int a0 = comp[u], a1 = comp[v];
            int b0 = -1, b1 = -1;
            for (int e = 0; e < 4; e++) {
              if (e != u && e != v) { if (b0 < 0) b0 = comp[e]; else b1 = comp[e]; }
            }
            int perm[7] = {a0, a1, b0, b1, x, y, z};
            int inv = 0;
            for (int q = 0; q < 7; q++)
              for (int r = q + 1; r < 7; r++)
                if (perm[q] > perm[r]) inv++;
            T.ts[c][t] = (inv & 1) ? -1.0f : 1.0f;
            T.ta[c][t] = (signed char)(6 * a0 - a0 * (a0 - 1) / 2 + (a1 - a0 - 1));
            T.tb[c][t] = (signed char)(6 * b0 - b0 * (b0 - 1) / 2 + (b1 - b0 - 1));
            t++;
          }
        c++;
      }
  int p = 0;
  for (int i = 0; i < 21; i++)
    for (int j = i; j < 21; j++) {
      T.p2i[p] = (unsigned char)i;
      T.p2j[p] = (unsigned char)j;
      p++;
    }
  for (; p < 256; p++) { T.p2i[p] = 0; T.p2j[p] = 0; }
  return T;
}

constexpr Tables hT = makeTables();
__constant__ Tables dT = makeTables();

// ======================= device scratch =========================================
#define NMAX   4096
#define NGRID  148
#define NPAIR  231
#define NK     77
#define TLD    79

__device__ float g_w[NMAX];
__device__ float g_psum[64];
__device__ float g_invsum;
__device__ float g_part[NGRID][256 * 80];
__device__ float g_S4[4][NPAIR * 80];
__device__ float g_S[NPAIR * NK];
__device__ float g_A[NK * NK];
__device__ float g_d[NK];
__device__ float g_e[NK];

// ======================= helpers ================================================
__device__ __forceinline__ uint32_t cvta_smem(const void* p) {
  uint32_t a;
  asm("{ .reg .u64 t; cvta.to.shared.u64 t, %1; cvt.u32.u64 %0, t; }"
      : "=r"(a) : "l"(p));
  return a;
}

__device__ __forceinline__ uint32_t bf16x2pack(float lo, float hi) {
  uint32_t r;
  asm("cvt.rn.bf16x2.f32 %0, %1, %2;" : "=r"(r) : "f"(hi), "f"(lo));
  return r;
}

#define LDSM_X4(r0, r1, r2, r3, addr) \
  asm volatile("ldmatrix.sync.aligned.m8n8.x4.shared.b16 {%0,%1,%2,%3}, [%4];" \
               : "=r"(r0), "=r"(r1), "=r"(r2), "=r"(r3) : "r"(addr))

#define MMA_BF16(c, a, b0_, b1_) \
  asm volatile("mma.sync.aligned.m16n8k16.row.col.f32.bf16.bf16.f32 " \
               "{%0,%1,%2,%3}, {%4,%5,%6,%7}, {%8,%9}, {%0,%1,%2,%3};" \
               : "+f"((c)[0]), "+f"((c)[1]), "+f"((c)[2]), "+f"((c)[3]) \
               : "r"((a)[0]), "r"((a)[1]), "r"((a)[2]), "r"((a)[3]), \
                 "r"(b0_), "r"(b1_))

// smem layout (bytes). Rows padded to 56 bf16 = 112 B (ldmatrix conflict-free).
#define A_ROWB   112
#define A_BYTES  (256 * A_ROWB)   // 28672
#define B_BYTES  (80 * A_ROWB)    // 8960
#define OFF_AH   0
#define OFF_AL   (OFF_AH + A_BYTES)        // 28672
#define OFF_BH   (OFF_AL + A_BYTES)        // 57344
#define OFF_BL   (OFF_BH + B_BYTES)        // 66304
#define OFF_WS   (OFF_BL + B_BYTES)        // 75264
#define SMEM_MAIN (OFF_WS + 441 * 4 + 92)  // 77120

// ======================= kernel 1a: per-sample volumes (full chip) ==============
__global__ void __launch_bounds__(256, 1)
k_vols(const float* __restrict__ metric, int n) {
  __shared__ float red[256];
  const int tid = threadIdx.x;
  const int idx = blockIdx.x * 256 + tid;
  float vol = 0.f;
  if (idx < n) {
    float a[7][7];
#pragma unroll
    for (int r = 0; r < 7; r++)
#pragma unroll
      for (int cc = 0; cc < 7; cc++) a[r][cc] = metric[idx * 49 + r * 7 + cc];
    float det = 1.f;
#pragma unroll
    for (int k = 0; k < 7; k++) {
      float mx = fabsf(a[k][k]);
      int piv = k;
#pragma unroll
      for (int r = k + 1; r < 7; r++) {
        float v = fabsf(a[r][k]);
        if (v > mx) { mx = v; piv = r; }
      }
#pragma unroll
      for (int r = k + 1; r < 7; r++) {
        if (piv == r) {
          det = -det;
#pragma unroll
          for (int cc = k; cc < 7; cc++) {
            float t = a[k][cc]; a[k][cc] = a[r][cc]; a[r][cc] = t;
          }
        }
      }
      float akk = a[k][k];
      det *= akk;
      float inv = (akk != 0.f) ? 1.f / akk : 0.f;
#pragma unroll
      for (int r = k + 1; r < 7; r++) {
        float f = a[r][k] * inv;
#pragma unroll
        for (int cc = k + 1; cc < 7; cc++) a[r][cc] = fmaf(-f, a[k][cc], a[r][cc]);
      }
    }
    vol = sqrtf(fabsf(det));
    g_w[idx] = vol;
  }
  red[tid] = vol;
  __syncthreads();
#pragma unroll
  for (int s = 128; s > 0; s >>= 1) {
    if (tid < s) red[tid] += red[tid + s];
    __syncthreads();
  }
  if (tid == 0) g_psum[blockIdx.x] = red[0];
}

__global__ void k_sumw(int nb) {
  if (threadIdx.x == 0) {
    float s = 0.f;
    for (int i = 0; i < nb; i++) s += g_psum[i];
    g_invsum = 1.f / s;
  }
}

// ======================= D-compute: fully unrolled ==============================
template <int C, int T>
__device__ __forceinline__ float dterms(const float (&wi)[21], const float (&wj)[21],
                                        float acc) {
  constexpr int a = hT.ta[C][T];
  constexpr int b = hT.tb[C][T];
  if constexpr (hT.ts[C][T] > 0.f)
    acc = fmaf(wi[a], wj[b], acc);
  else
    acc = fmaf(-wi[a], wj[b], acc);
  if constexpr (T + 1 < 6) return dterms<C, T + 1>(wi, wj, acc);
  return acc;
}

template <int C, int CBASE, int CEND>
__device__ __forceinline__ void dArr(float (&dv)[18], const float (&wi)[21],
                                     const float (&wj)[21]) {
  dv[C - CBASE] = dterms<C, 0>(wi, wj, 0.0f);
  if constexpr (C + 1 < CEND) dArr<C + 1, CBASE, CEND>(dv, wi, wj);
}

// ======================= kernel 2: mma.sync bf16-split GEMM =====================
// grid 148 x 512 (16 warps). Register accumulators S[256x80] per block across n.
// Per n: stage B = Phi*wn (bf16 hi/lo), D-phase -> A (bf16 hi/lo), then
// per warp 36 ldmatrix.x4 + 90 mma (3 kchunks x 10 ntiles x {DhPh,DhPl,DlPh}).
__global__ void __launch_bounds__(512, 1)
k_main(const float* __restrict__ omega, const float* __restrict__ Phi, int n,
       int chunk) {
  extern __shared__ char smc[];
  const int tid  = threadIdx.x;
  const int w    = tid >> 5;
  const int lane = tid & 31;
  const uint32_t smb = cvta_smem(smc);

  // zero A/B tiles once (k-padding + B n-padding persist as zeros)
  for (int i = tid; i < OFF_WS / 4; i += 512) ((uint32_t*)smc)[i] = 0u;

  int n0 = blockIdx.x * chunk;
  int n1 = n0 + chunk;
  if (n1 > n) n1 = n;

  const int myPair = tid & 255;
  const int pi = dT.p2i[myPair];
  const int pj = dT.p2j[myPair];
  float* Ws = (float*)(smc + OFF_WS);

  // B staging map: idx = tid + j*512 -> (kout, c); byte offset kout*112 + c*2
  uint32_t bOff[6];
  bool bAct[6];
#pragma unroll
  for (int j = 0; j < 6; j++) {
    int idx = tid + j * 512;
    bAct[j] = idx < 2695;
    int k = idx / 35;
    int c = idx - k * 35;
    bOff[j] = (uint32_t)(k * A_ROWB + c * 2);
  }

  // ldmatrix lane addresses (fixed per thread)
  const uint32_t aRow  = (uint32_t)(w * 16 + ((lane >> 3) & 1) * 8 + (lane & 7));
  const uint32_t aAddr = smb + OFF_AH + aRow * A_ROWB + (uint32_t)(lane >> 4) * 16;
  const uint32_t bRow  = (uint32_t)(((lane >> 4) & 1) * 8 + (lane & 7));
  const uint32_t bAddr = smb + OFF_BH + bRow * A_ROWB + (uint32_t)((lane >> 3) & 1) * 16;

  float acc[10][4];
#pragma unroll
  for (int a = 0; a < 10; a++)
#pragma unroll
    for (int b = 0; b < 4; b++) acc[a][b] = 0.f;

  // prefetch first n
  float rO = 0.f, rP[6], rWn = 0.f;
#pragma unroll
  for (int j = 0; j < 6; j++) rP[j] = 0.f;
  if (n0 < n1) {
    const float* og = omega + (size_t)n0 * 441;
    if (tid < 441) rO = og[tid];
    const float* pg = Phi + (size_t)n0 * 2695;
#pragma unroll
    for (int j = 0; j < 6; j++)
      if (bAct[j]) rP[j] = pg[tid + j * 512];
    rWn = g_w[n0];
  }

#pragma unroll 1
  for (int nn = n0; nn < n1; nn++) {
    __syncthreads();   // tiles free from previous iteration's ldmatrix reads

    if (tid < 441) Ws[tid] = rO;
    {
      const float wn = rWn;
#pragma unroll
      for (int j = 0; j < 6; j++) {
        if (bAct[j]) {
          float v = rP[j] * wn;
          __nv_bfloat16 bh = __float2bfloat16(v);
          float res = v - __bfloat162float(bh);
          __nv_bfloat16 bl = __float2bfloat16(res);
          *(__nv_bfloat16*)(smc + OFF_BH + bOff[j]) = bh;
          *(__nv_bfloat16*)(smc + OFF_BL + bOff[j]) = bl;
        }
      }
    }
    __syncthreads();   // Ws + B visible

    {  // D-phase: fp32 -> bf16 hi/lo into A tiles
      float wi[21], wj[21];
      const float* Wi = &Ws[pi * 21];
      const float* Wj = &Ws[pj * 21];
#pragma unroll
      for (int a = 0; a < 21; a++) { wi[a] = Wi[a]; wj[a] = Wj[a]; }
      float dv[18];
      int cb;
      if (tid < 256) { dArr<0, 0, 18>(dv, wi, wj); cb = 0; }
      else           { dArr<18, 18, 35>(dv, wi, wj); dv[17] = 0.f; cb = 18; }
      const uint32_t rowBase = (uint32_t)(myPair * A_ROWB + cb * 2);
#pragma unroll
      for (int u = 0; u < 9; u++) {
        float d0 = dv[2 * u], d1 = dv[2 * u + 1];
        uint32_t hw = bf16x2pack(d0, d1);
        float r0 = d0 - __uint_as_float(hw << 16);
        float r1 = d1 - __uint_as_float(hw & 0xffff0000u);
        uint32_t lw = bf16x2pack(r0, r1);
        uint32_t off = rowBase + 4 * u;
        *(uint32_t*)(smc + OFF_AH + off) = hw;
        *(uint32_t*)(smc + OFF_AL + off) = lw;
      }
    }

    {  // prefetch next n (overlaps with barrier + GEMM)
      int nx = (nn + 1 < n1) ? nn + 1 : nn;
      const float* og = omega + (size_t)nx * 441;
      if (tid < 441) rO = og[tid];
      const float* pg = Phi + (size_t)nx * 2695;
#pragma unroll
      for (int j = 0; j < 6; j++)
        if (bAct[j]) rP[j] = pg[tid + j * 512];
      rWn = g_w[nx];
    }
    __syncthreads();   // A tiles visible

    // GEMM: per warp 16x80 tile, K=48
#pragma unroll
    for (int ks = 0; ks < 3; ks++) {
      uint32_t ah[4], al[4];
      LDSM_X4(ah[0], ah[1], ah[2], ah[3], aAddr + ks * 32);
      LDSM_X4(al[0], al[1], al[2], al[3], aAddr + A_BYTES + ks * 32);
#pragma unroll
      for (int tp = 0; tp < 5; tp++) {
        uint32_t bh[4], bl[4];
        uint32_t ba = bAddr + (uint32_t)(tp * 16 * A_ROWB) + ks * 32;
        LDSM_X4(bh[0], bh[1], bh[2], bh[3], ba);
        LDSM_X4(bl[0], bl[1], bl[2], bl[3], ba + B_BYTES);
        MMA_BF16(acc[2 * tp],     ah, bh[0], bh[1]);
        MMA_BF16(acc[2 * tp],     ah, bl[0], bl[1]);
        MMA_BF16(acc[2 * tp],     al, bh[0], bh[1]);
        MMA_BF16(acc[2 * tp + 1], ah, bh[2], bh[3]);
        MMA_BF16(acc[2 * tp + 1], ah, bl[2], bl[3]);
        MMA_BF16(acc[2 * tp + 1], al, bh[2], bh[3]);
      }
    }
  }

  // epilogue: spill register accumulators to g_part
  {
    const int g = lane >> 2, t = lane & 3;
    const int r0 = w * 16 + g, r1 = r0 + 8;
    float* dst = g_part[blockIdx.x];
#pragma unroll
    for (int nt = 0; nt < 10; nt++) {
      int col = nt * 8 + 2 * t;
      *(float2*)&dst[r0 * 80 + col] = make_float2(acc[nt][0], acc[nt][1]);
      *(float2*)&dst[r1 * 80 + col] = make_float2(acc[nt][2], acc[nt][3]);
    }
  }
}

// ======================= kernel 3a: reduce partials (4-way n-chunk) =============
__global__ void __launch_bounds__(128, 4)
k_reduceS() {
  const int t = blockIdx.x * 128 + threadIdx.x;
  if (t >= NPAIR * 20) return;
  const int p = t / 20;
  const int q = t - p * 20;
  const int b0 = blockIdx.y * 37;
  float4 s = make_float4(0.f, 0.f, 0.f, 0.f);
#pragma unroll 4
  for (int b = 0; b < 37; b++) {
    float4 v = *(const float4*)&g_part[b0 + b][p * 80 + q * 4];
    s.x += v.x; s.y += v.y; s.z += v.z; s.w += v.w;
  }
  *(float4*)&g_S4[blockIdx.y][p * 80 + q * 4] = s;
}

// ======================= kernel 3b: emit Y + final S ============================
__global__ void k_emitY(float* __restrict__ out, int writeY) {
  int idx = blockIdx.x * blockDim.x + threadIdx.x;
  if (idx >= 441 * 77) return;
  const float inv = g_invsum;
  int i = idx / 1617;
  int rem = idx - i * 1617;
  int j = rem / 77;
  int k = rem - j * 77;
  int lo = i < j ? i : j;
  int hi = i < j ? j : i;
  int p = lo * 21 - lo * (lo - 1) / 2 + (hi - lo);
  float s = (g_S4[0][p * 80 + k] + g_S4[1][p * 80 + k]) +
            (g_S4[2][p * 80 + k] + g_S4[3][p * 80 + k]);
  s *= inv;
  if (writeY) out[idx] = (j >= i) ? s : -s;
  if (i <= j) g_S[p * 77 + k] = s;
}

// ======================= kernel 4: build M = S^T diag(m) S ======================
__global__ void __launch_bounds__(128, 1)
k_buildM(float* __restrict__ out, int oM) {
  __shared__ float cs[NPAIR];
  const int k = blockIdx.x;
  const int tid = threadIdx.x;
  for (int p = tid; p < NPAIR; p += 128) {
    float wgt = (dT.p2i[p] == dT.p2j[p]) ? 1.f : 2.f;
    cs[p] = wgt * g_S[p * 77 + k];
  }
  __syncthreads();
  if (tid < 77) {
    float a0 = 0.f, a1 = 0.f, a2 = 0.f, a3 = 0.f;
    int p = 0;
#pragma unroll 4
    for (; p + 4 <= NPAIR; p += 4) {
      a0 = fmaf(cs[p],     g_S[p * 77 + tid],       a0);
      a1 = fmaf(cs[p + 1], g_S[(p + 1) * 77 + tid], a1);
      a2 = fmaf(cs[p + 2], g_S[(p + 2) * 77 + tid], a2);
      a3 = fmaf(cs[p + 3], g_S[(p + 3) * 77 + tid], a3);
    }
    for (; p < NPAIR; p++) a0 = fmaf(cs[p], g_S[p * 77 + tid], a0);
    float v = (a0 + a1) + (a2 + a3);
    out[oM + k * 77 + tid] = v;
    g_A[k * 77 + tid] = v;
  }
}

// ======================= kernel 5: Householder tridiagonalization ===============
__device__ __forceinline__ float blockReduce256(float v, volatile float* red,
                                                int tid) {
  __syncthreads();
#pragma unroll
  for (int o = 16; o; o >>= 1) v += __shfl_down_sync(0xffffffffu, v, o);
  if ((tid & 31) == 0) red[tid >> 5] = v;
  __syncthreads();
  if (tid < 8) {
    float r = red[tid];
#pragma unroll
    for (int o = 4; o; o >>= 1) r += __shfl_down_sync(0xffu, r, o);
    if (tid == 0) red[0] = r;
  }
  __syncthreads();
  return red[0];
}

__global__ void __launch_bounds__(256, 1) k_tridiag() {
  __shared__ float A[NK * TLD];
  __shared__ float us[80], ps[80], pp[80];
  __shared__ float red[8];
  __shared__ float dd[NK], ee[NK];
  __shared__ float scA, scTb;
  __shared__ int   skip;
  const int tid  = threadIdx.x;
  const int lane = tid & 31;
  const int warp = tid >> 5;
  const int rrow = tid >> 1;
  const int rq   = tid & 1;

  for (int idx = tid; idx < NK * NK; idx += 256) {
    int r = idx / NK, c = idx - r * NK;
    A[r * TLD + c] = g_A[idx];
  }
  __syncthreads();

#pragma unroll 1
  for (int k = 0; k < 75; k++) {
    const int m = 76 - k;
    float v = 0.f;
    if (tid < m) v = A[(k + 1 + tid) * TLD + k];
    float sigma = blockReduce256(v * v, red, tid);
    if (tid == 0) {
      dd[k] = A[k * TLD + k];
      if (sigma < 1e-30f) {
        ee[k] = 0.f;
        skip = 1;
      } else {
        float v0 = A[(k + 1) * TLD + k];
        float alpha = -copysignf(sqrtf(sigma), v0);
        ee[k] = alpha;
        scA = alpha;
        float beta = 2.f * (sigma - v0 * alpha);
        scTb = 2.f / beta;
        skip = 0;
      }
    }
    __syncthreads();
    if (skip) continue;

    if (tid < m) us[tid] = (tid == 0) ? v - scA : v;
    __syncthreads();

    {
      float a0 = 0.f, a1 = 0.f, a2 = 0.f, a3 = 0.f;
      if (rrow < m) {
        const float* row = &A[(k + 1 + rrow) * TLD + (k + 1)];
        int j = rq;
        for (; j + 6 < m; j += 8) {
          a0 = fmaf(row[j],     us[j],     a0);
          a1 = fmaf(row[j + 2], us[j + 2], a1);
          a2 = fmaf(row[j + 4], us[j + 4], a2);
          a3 = fmaf(row[j + 6], us[j + 6], a3);
        }
        for (; j < m; j += 2) a0 = fmaf(row[j], us[j], a0);
      }
      float s = (a0 + a1) + (a2 + a3);
      s += __shfl_xor_sync(0xffffffffu, s, 1);
      if (rrow < m && rq == 0) pp[rrow] = s * scTb;
    }
    __syncthreads();
    float upT = blockReduce256((tid < m) ? pp[tid] * us[tid] : 0.f, red, tid);
    if (tid < m) ps[tid] = pp[tid] - (upT * scTb * 0.5f) * us[tid];
    __syncthreads();

    for (int i = warp; i < m; i += 8) {
      const float ui = us[i], pi_ = ps[i];
      float* rowA = &A[(k + 1 + i) * TLD + (k + 1)];
      for (int j = lane; j < m; j += 32)
        rowA[j] -= ui * ps[j] + pi_ * us[j];
    }
    __syncthreads();
  }

  if (tid == 0) {
    dd[75] = A[75 * TLD + 75];
    ee[75] = A[76 * TLD + 75];
    dd[76] = A[76 * TLD + 76];
    ee[76] = 0.f;
  }
  __syncthreads();
  if (tid < NK) {
    g_d[tid] = dd[tid];
    g_e[tid] = ee[tid];
  }
}

// ======================= kernel 6: Sturm multisection eigenvalues ===============
#define NPROBE 13
#define NROUND 10

__global__ void __launch_bounds__(1024, 1)
k_bisect(float* __restrict__ out, int oE) {
  __shared__ float d_s[NK], e2_s[NK];
  __shared__ float lo_s[NK], hi_s[NK];
  __shared__ float xs[NK * NPROBE];
  __shared__ int   cs[NK * NPROBE];
  __shared__ float gl_s, gh_s, piv_s;
  const int tid = threadIdx.x;
  const int g = tid / NPROBE;
  const int j = tid - g * NPROBE;
  const bool act = (g < NK);

  if (tid < NK) {
    d_s[tid] = g_d[tid];
    float e = g_e[tid];
    e2_s[tid] = e * e;
  }
  __syncthreads();

  if (tid == 0) {
    float gl = 3.4e38f, gh = -3.4e38f, me2 = 0.f;
    for (int i = 0; i < NK; i++) {
      float eprev = (i > 0) ? sqrtf(e2_s[i - 1]) : 0.f;
      float ecur  = (i < 76) ? sqrtf(e2_s[i]) : 0.f;
      float r = eprev + ecur;
      gl = fminf(gl, d_s[i] - r);
      gh = fmaxf(gh, d_s[i] + r);
      me2 = fmaxf(me2, e2_s[i]);
    }
    float wid = fmaxf(gh - gl, 1e-20f);
    gl_s = gl - 1e-3f * wid;
    gh_s = gh + 1e-3f * wid;
    piv_s = fmaxf(me2 * 1.2e-38f, 1e-37f);
  }
  __syncthreads();
  if (tid < NK) { lo_s[tid] = gl_s; hi_s[tid] = gh_s; }
  __syncthreads();

  const float pivmin = piv_s;
  const float cj = (float)(j + 1) / (float)(NPROBE + 1);

#pragma unroll 1
  for (int r = 0; r < NROUND; r++) {
    if (act) {
      float lo = lo_s[g], hi = hi_s[g];
      float x = lo + (hi - lo) * cj;
      xs[tid] = x;
      float q = d_s[0] - x;
      int cnt = (q < 0.f);
#pragma unroll 4
      for (int i = 1; i < NK; i++) {
        float aq = fabsf(q);
        if (aq < pivmin) q = -pivmin;
        q = d_s[i] - x - __fdividef(e2_s[i - 1], q);
        cnt += (q < 0.f);
      }
      cs[tid] = cnt;
    }
    __syncthreads();
    if (act && j == 0) {
      float lo = lo_s[g], hi = hi_s[g];
      for (int jj = 0; jj < NPROBE; jj++) {
        int c = cs[g * NPROBE + jj];
        float x = xs[g * NPROBE + jj];
        if (c <= g) lo = x;
        else { hi = x; break; }
      }
      lo_s[g] = lo;
      hi_s[g] = hi;
    }
    __syncthreads();
  }

  if (act && j == 0) out[oE + (76 - g)] = 0.5f * (lo_s[g] + hi_s[g]);
}

// ======================= launch =================================================
extern "C" void kernel_launch(void* const* d_in, const int* in_sizes, int n_in,
                              void* d_out, int out_size) {
  const float* omega  = (const float*)d_in[0];
  const float* Phi    = (const float*)d_in[1];
  const float* metric = (const float*)d_in[2];
  int n = in_sizes[2] / 49;
  if (n > NMAX) n = NMAX;

  float* out = (float*)d_out;
  int oE = out_size - 77;
  int oM = oE - 77 * 77;
  int writeY = (out_size >= 33957 + 77 * 77 + 77) ? 1 : 0;

  int nb = (n + 255) / 256;
  k_vols<<<nb, 256>>>(metric, n);
  k_sumw<<<1, 32>>>(nb);

  int chunk = (n + NGRID - 1) / NGRID;
  cudaFuncSetAttribute(k_main, cudaFuncAttributeMaxDynamicSharedMemorySize,
                       SMEM_MAIN);
  k_main<<<NGRID, 512, SMEM_MAIN>>>(omega, Phi, n, chunk);

  k_reduceS<<<dim3((NPAIR * 20 + 127) / 128, 4), 128>>>();
  k_emitY<<<(441 * 77 + 255) / 256, 256>>>(out, writeY);

  k_buildM<<<77, 128>>>(out, oM);
  k_tridiag<<<1, 256>>>();
  k_bisect<<<1, 1024>>>(out, oE);
}